// round 1
// baseline (speedup 1.0000x reference)
#include <cuda_runtime.h>
#include <math.h>
#include <stdint.h>

// ---------------- problem constants ----------------
#define NB    4        // batch
#define SP    4096     // H*W
#define MTOT  16384    // NB*SP
#define DIMC  256
#define HID_N 1024

// ---------------- scratch (static device globals; no allocs) ----------------
__device__ float g_xall[(size_t)MTOT * 512];   // normalized [xq | xkv], NHWC512
__device__ float g_q   [(size_t)MTOT * 256];   // q, scaled, NHWC
__device__ float g_kv  [(size_t)MTOT * 512];   // k(0:256) v(256:512), NHWC
__device__ float g_h1  [(size_t)MTOT * 256];   // relu(conv3x3), NHWC
__device__ float g_offs[(size_t)MTOT * 18];    // (px,py) x 9, per pixel
__device__ float g_att [(size_t)MTOT * 256];   // attention out, NHWC
__device__ float g_xres[(size_t)MTOT * 256];   // x_q + proj, NHWC
__device__ float g_xn2 [(size_t)MTOT * 256];   // norm2(xres), NHWC
__device__ float g_hid [(size_t)MTOT * 1024];  // gelu(fc1), NHWC
__device__ float g_wr  [256 * 4608];           // conv weights repacked [O][(ky*3+kx)*512+c]
__device__ float g_st1 [16];                   // gn1: 8 x (mean, rstd)
__device__ float g_st2 [8];                    // gn2: 4 x (mean, rstd)

// ---------------- conv weight repack ----------------
__global__ void repack_k(const float* __restrict__ w, float* __restrict__ wr) {
    int id = blockIdx.x * blockDim.x + threadIdx.x;
    if (id >= 256 * 4608) return;
    int o = id / 4608, k = id - o * 4608;
    int nb = k >> 9, c = k & 511;
    int ky = nb / 3, kx = nb - ky * 3;
    wr[id] = w[((size_t)o * 512 + c) * 9 + ky * 3 + kx];
}

// ---------------- groupnorm (1 group = whole sample) stats ----------------
// grid.x = ntensors*4; tensor = bi>>2, batch = bi&3. Each source slab is 2^20 contiguous floats.
__global__ void gn_stats_k(const float* __restrict__ A, const float* __restrict__ Bsrc,
                           float* __restrict__ stats) {
    int bi = blockIdx.x;
    int tensor = bi >> 2, batch = bi & 3;
    const float* src = (tensor == 0 ? A : Bsrc) + ((size_t)batch << 20);
    const float4* p4 = reinterpret_cast<const float4*>(src);
    float s = 0.f, s2 = 0.f;
    for (int i = threadIdx.x; i < (1 << 18); i += blockDim.x) {
        float4 v = p4[i];
        s  += v.x + v.y + v.z + v.w;
        s2 += v.x * v.x + v.y * v.y + v.z * v.z + v.w * v.w;
    }
    __shared__ float sh1[512], sh2[512];
    sh1[threadIdx.x] = s; sh2[threadIdx.x] = s2;
    __syncthreads();
    for (int st = 256; st > 0; st >>= 1) {
        if (threadIdx.x < st) { sh1[threadIdx.x] += sh1[threadIdx.x + st];
                                sh2[threadIdx.x] += sh2[threadIdx.x + st]; }
        __syncthreads();
    }
    if (threadIdx.x == 0) {
        float inv = 1.f / 1048576.f;
        float mu = sh1[0] * inv;
        float var = sh2[0] * inv - mu * mu;
        stats[bi * 2] = mu;
        stats[bi * 2 + 1] = rsqrtf(var + 1e-5f);
    }
}

// ---------------- normalize + NCHW->NHWC pack (both tensors into g_xall) ----------------
// grid (128, 8, 8): z = tensor*4 + batch; block (32,8)
__global__ void norm_pack_k(const float* __restrict__ xq, const float* __restrict__ xkv,
                            const float* __restrict__ stats, const float* __restrict__ w,
                            const float* __restrict__ bb, float* __restrict__ xall) {
    __shared__ float tile[32][33];
    int bz = blockIdx.z;
    int tensor = bz >> 2, batch = bz & 3;
    const float* src = (tensor == 0 ? xq : xkv) + ((size_t)batch << 20);
    float mu = stats[bz * 2], rstd = stats[bz * 2 + 1];
    int s0 = blockIdx.x * 32, c0 = blockIdx.y * 32;
    int tx = threadIdx.x, ty = threadIdx.y;
#pragma unroll
    for (int k = 0; k < 4; k++) {
        int c = c0 + ty + k * 8;
        tile[ty + k * 8][tx] = src[(size_t)c * 4096 + s0 + tx];
    }
    __syncthreads();
#pragma unroll
    for (int k = 0; k < 4; k++) {
        int sl = ty + k * 8;
        int c = c0 + tx;
        float v = (tile[tx][sl] - mu) * rstd * w[c] + bb[c];
        xall[(((size_t)batch * 4096 + s0 + sl) << 9) + tensor * 256 + c] = v;
    }
}

// ---------------- norm2 (NHWC elementwise) ----------------
__global__ void norm2_k(const float* __restrict__ xres, const float* __restrict__ stats,
                        const float* __restrict__ w, const float* __restrict__ bb,
                        float* __restrict__ xn) {
    int id = blockIdx.x * blockDim.x + threadIdx.x;
    if (id >= MTOT * 256) return;
    int b = id >> 20, c = id & 255;
    xn[id] = (xres[id] - stats[b * 2]) * stats[b * 2 + 1] * w[c] + bb[c];
}

// ---------------- SGEMM: C[M,N] = A[M,K] @ W[N,K]^T + bias, epilogue by MODE ----------------
// MODE 0: plain   1: *scale   2: relu   3: gelu(exact)
// MODE 4: + residual from NCHW R, store NHWC
// MODE 5: + residual from NHWC R, store NCHW
constexpr int BM = 64, BN = 64, BK = 16;

template <int MODE, bool IM2COL>
__global__ void __launch_bounds__(256) gemm_k(
    const float* __restrict__ A, const float* __restrict__ W,
    const float* __restrict__ bias, float* __restrict__ C,
    int N, int K, int lda, const float* __restrict__ R, float scale) {
    __shared__ float As[BK][BM + 4];
    __shared__ float Ws[BK][BN + 4];
    const int tid = threadIdx.x;
    const int bm = blockIdx.y * BM, bn = blockIdx.x * BN;
    const int rm = (tid >> 4) * 4, rn = (tid & 15) * 4;
    const int lr = tid >> 2, lk = (tid & 3) * 4;
    float acc[4][4] = {};

    int ib = 0, iy = 0, ix = 0;
    if (IM2COL) {
        int m = bm + lr;
        ib = m >> 12; int s = m & 4095; iy = s >> 6; ix = s & 63;
    }
    for (int k0 = 0; k0 < K; k0 += BK) {
        // --- A tile ---
        if (!IM2COL) {
            float4 v = *reinterpret_cast<const float4*>(A + (size_t)(bm + lr) * lda + k0 + lk);
            As[lk][lr] = v.x; As[lk + 1][lr] = v.y; As[lk + 2][lr] = v.z; As[lk + 3][lr] = v.w;
        } else {
            int kk = k0 + lk;
            int nb = kk >> 9;                  // 4-element group never crosses a 512 boundary
            int c = kk & 511;
            int dy = nb / 3 - 1, dx = nb - (nb / 3) * 3 - 1;
            int yy = iy + dy, xx = ix + dx;
            if (yy >= 0 && yy < 64 && xx >= 0 && xx < 64) {
                float4 v = *reinterpret_cast<const float4*>(
                    A + (((size_t)ib * 4096 + yy * 64 + xx) << 9) + c);
                As[lk][lr] = v.x; As[lk + 1][lr] = v.y; As[lk + 2][lr] = v.z; As[lk + 3][lr] = v.w;
            } else {
                As[lk][lr] = 0.f; As[lk + 1][lr] = 0.f; As[lk + 2][lr] = 0.f; As[lk + 3][lr] = 0.f;
            }
        }
        // --- W tile ---
        {
            float4 v = *reinterpret_cast<const float4*>(W + (size_t)(bn + lr) * K + k0 + lk);
            Ws[lk][lr] = v.x; Ws[lk + 1][lr] = v.y; Ws[lk + 2][lr] = v.z; Ws[lk + 3][lr] = v.w;
        }
        __syncthreads();
#pragma unroll
        for (int kk = 0; kk < BK; kk++) {
            float4 a = *reinterpret_cast<const float4*>(&As[kk][rm]);
            float4 w = *reinterpret_cast<const float4*>(&Ws[kk][rn]);
            acc[0][0] += a.x * w.x; acc[0][1] += a.x * w.y; acc[0][2] += a.x * w.z; acc[0][3] += a.x * w.w;
            acc[1][0] += a.y * w.x; acc[1][1] += a.y * w.y; acc[1][2] += a.y * w.z; acc[1][3] += a.y * w.w;
            acc[2][0] += a.z * w.x; acc[2][1] += a.z * w.y; acc[2][2] += a.z * w.z; acc[2][3] += a.z * w.w;
            acc[3][0] += a.w * w.x; acc[3][1] += a.w * w.y; acc[3][2] += a.w * w.z; acc[3][3] += a.w * w.w;
        }
        __syncthreads();
    }
#pragma unroll
    for (int i = 0; i < 4; i++) {
        int m = bm + rm + i;
#pragma unroll
        for (int j = 0; j < 4; j++) {
            int n = bn + rn + j;
            float v = acc[i][j] + bias[n];
            if (MODE == 1) v *= scale;
            if (MODE == 2) v = v > 0.f ? v : 0.f;
            if (MODE == 3) v = 0.5f * v * (1.f + erff(v * 0.70710678118654752f));
            if (MODE == 4) v += R[((size_t)(m >> 12) * 256 + n) * 4096 + (m & 4095)];
            if (MODE == 5) v += R[(size_t)m * 256 + n];
            if (MODE == 5)
                C[((size_t)(m >> 12) * 256 + n) * 4096 + (m & 4095)] = v;
            else
                C[(size_t)m * (size_t)N + n] = v;
        }
    }
}

// ---------------- offset head: (M,18) = h1 @ off2_w^T + b ----------------
__global__ void off2_k(const float* __restrict__ h1, const float* __restrict__ w,
                       const float* __restrict__ bias, float* __restrict__ offs) {
    int id = blockIdx.x * blockDim.x + threadIdx.x;
    if (id >= MTOT * 18) return;
    int m = id / 18, n = id - m * 18;
    const float4* a = reinterpret_cast<const float4*>(h1 + (size_t)m * 256);
    const float4* ww = reinterpret_cast<const float4*>(w + (size_t)n * 256);
    float s = bias[n];
#pragma unroll 8
    for (int k = 0; k < 64; k++) {
        float4 av = a[k], wv = ww[k];
        s += av.x * wv.x + av.y * wv.y + av.z * wv.z + av.w * wv.w;
    }
    offs[id] = s;
}

// ---------------- fused bilinear-sample + 9-way attention ----------------
// One warp per output pixel. Thread t owns channels cc = 8t..8t+7 (head = cc%8, c = cc/8).
#define LOAD8(dst, ptr)                                                     \
    {                                                                       \
        float4 _u0 = *reinterpret_cast<const float4*>(ptr);                 \
        float4 _u1 = *reinterpret_cast<const float4*>((ptr) + 4);           \
        dst[0] = _u0.x; dst[1] = _u0.y; dst[2] = _u0.z; dst[3] = _u0.w;     \
        dst[4] = _u1.x; dst[5] = _u1.y; dst[6] = _u1.z; dst[7] = _u1.w;     \
    }

__global__ void __launch_bounds__(256) attn_k(
    const float* __restrict__ qb, const float* __restrict__ kv,
    const float* __restrict__ offs, float* __restrict__ outp) {
    __shared__ float sh[8][9][8];
    const int warp = threadIdx.x >> 5, lane = threadIdx.x & 31;
    const int p = blockIdx.x * 8 + warp;
    const int b = p >> 12, s = p & 4095, y = s >> 6, x = s & 63;
    const float* kvb = kv + (((size_t)b << 12) << 9);

    float qr[8];
    LOAD8(qr, qb + (size_t)p * 256 + lane * 8);

    // ---------- pass 1: logits ----------
    for (int o = 0; o < 9; o++) {
        int ys = y + o / 3 - 1, xs = x + o % 3 - 1;
        float prod[8] = {0.f, 0.f, 0.f, 0.f, 0.f, 0.f, 0.f, 0.f};
        if (ys >= 0 && ys < 64 && xs >= 0 && xs < 64) {
            const float* op = offs + (size_t)((b << 12) + (ys << 6) + xs) * 18 + 2 * o;
            float px = op[0], py = op[1];
            float y0f = floorf(py), x0f = floorf(px);
            float wy = py - y0f, wx = px - x0f;
            int y0 = (int)y0f, x0 = (int)x0f;
            float w00 = (1.f - wy) * (1.f - wx), w01 = (1.f - wy) * wx;
            float w10 = wy * (1.f - wx), w11 = wy * wx;
            bool vy0 = (y0 >= 0) && (y0 < 64), vy1 = (y0 + 1 >= 0) && (y0 + 1 < 64);
            bool vx0 = (x0 >= 0) && (x0 < 64), vx1 = (x0 + 1 >= 0) && (x0 + 1 < 64);
            w00 = (vy0 && vx0) ? w00 : 0.f; w01 = (vy0 && vx1) ? w01 : 0.f;
            w10 = (vy1 && vx0) ? w10 : 0.f; w11 = (vy1 && vx1) ? w11 : 0.f;
            int y0c = min(max(y0, 0), 63), y1c = min(max(y0 + 1, 0), 63);
            int x0c = min(max(x0, 0), 63), x1c = min(max(x0 + 1, 0), 63);
            float c00[8], c01[8], c10[8], c11[8];
            LOAD8(c00, kvb + ((size_t)((y0c << 6) + x0c) << 9) + lane * 8);
            LOAD8(c01, kvb + ((size_t)((y0c << 6) + x1c) << 9) + lane * 8);
            LOAD8(c10, kvb + ((size_t)((y1c << 6) + x0c) << 9) + lane * 8);
            LOAD8(c11, kvb + ((size_t)((y1c << 6) + x1c) << 9) + lane * 8);
#pragma unroll
            for (int h = 0; h < 8; h++) {
                float kvv = w00 * c00[h] + w01 * c01[h] + w10 * c10[h] + w11 * c11[h];
                prod[h] = qr[h] * kvv;
            }
        }
#pragma unroll
        for (int off = 16; off > 0; off >>= 1)
#pragma unroll
            for (int h = 0; h < 8; h++)
                prod[h] += __shfl_xor_sync(0xffffffffu, prod[h], off);
        if (lane == 0) {
#pragma unroll
            for (int h = 0; h < 8; h++) sh[warp][o][h] = prod[h];
        }
    }
    __syncwarp();
    // ---------- softmax over o (9) per head ----------
    if (lane < 8) {
        float e[9]; float mx = -1e30f;
#pragma unroll
        for (int o = 0; o < 9; o++) { e[o] = sh[warp][o][lane]; mx = fmaxf(mx, e[o]); }
        float sm = 0.f;
#pragma unroll
        for (int o = 0; o < 9; o++) { e[o] = expf(e[o] - mx); sm += e[o]; }
        float inv = 1.f / sm;
#pragma unroll
        for (int o = 0; o < 9; o++) sh[warp][o][lane] = e[o] * inv;
    }
    __syncwarp();
    // ---------- pass 2: weighted V ----------
    float acc[8] = {0.f, 0.f, 0.f, 0.f, 0.f, 0.f, 0.f, 0.f};
    for (int o = 0; o < 9; o++) {
        int ys = y + o / 3 - 1, xs = x + o % 3 - 1;
        if (ys < 0 || ys >= 64 || xs < 0 || xs >= 64) continue;
        const float* op = offs + (size_t)((b << 12) + (ys << 6) + xs) * 18 + 2 * o;
        float px = op[0], py = op[1];
        float y0f = floorf(py), x0f = floorf(px);
        float wy = py - y0f, wx = px - x0f;
        int y0 = (int)y0f, x0 = (int)x0f;
        float w00 = (1.f - wy) * (1.f - wx), w01 = (1.f - wy) * wx;
        float w10 = wy * (1.f - wx), w11 = wy * wx;
        bool vy0 = (y0 >= 0) && (y0 < 64), vy1 = (y0 + 1 >= 0) && (y0 + 1 < 64);
        bool vx0 = (x0 >= 0) && (x0 < 64), vx1 = (x0 + 1 >= 0) && (x0 + 1 < 64);
        w00 = (vy0 && vx0) ? w00 : 0.f; w01 = (vy0 && vx1) ? w01 : 0.f;
        w10 = (vy1 && vx0) ? w10 : 0.f; w11 = (vy1 && vx1) ? w11 : 0.f;
        int y0c = min(max(y0, 0), 63), y1c = min(max(y0 + 1, 0), 63);
        int x0c = min(max(x0, 0), 63), x1c = min(max(x0 + 1, 0), 63);
        float c00[8], c01[8], c10[8], c11[8];
        LOAD8(c00, kvb + ((size_t)((y0c << 6) + x0c) << 9) + 256 + lane * 8);
        LOAD8(c01, kvb + ((size_t)((y0c << 6) + x1c) << 9) + 256 + lane * 8);
        LOAD8(c10, kvb + ((size_t)((y1c << 6) + x0c) << 9) + 256 + lane * 8);
        LOAD8(c11, kvb + ((size_t)((y1c << 6) + x1c) << 9) + 256 + lane * 8);
#pragma unroll
        for (int h = 0; h < 8; h++) {
            float vv = w00 * c00[h] + w01 * c01[h] + w10 * c10[h] + w11 * c11[h];
            acc[h] += sh[warp][o][h] * vv;
        }
    }
    float4* po = reinterpret_cast<float4*>(outp + (size_t)p * 256 + lane * 8);
    po[0] = make_float4(acc[0], acc[1], acc[2], acc[3]);
    po[1] = make_float4(acc[4], acc[5], acc[6], acc[7]);
}

// ---------------- host ----------------
extern "C" void kernel_launch(void* const* d_in, const int* in_sizes, int n_in,
                              void* d_out, int out_size) {
    const float* x_q    = (const float*)d_in[0];
    const float* x_kv   = (const float*)d_in[1];
    const float* n1w    = (const float*)d_in[2];
    const float* n1b    = (const float*)d_in[3];
    const float* q_w    = (const float*)d_in[4];
    const float* q_b    = (const float*)d_in[5];
    const float* kv_w   = (const float*)d_in[6];
    const float* kv_b   = (const float*)d_in[7];
    const float* off1_w = (const float*)d_in[8];
    const float* off1_b = (const float*)d_in[9];
    const float* off2_w = (const float*)d_in[10];
    const float* off2_b = (const float*)d_in[11];
    const float* proj_w = (const float*)d_in[12];
    const float* proj_b = (const float*)d_in[13];
    const float* n2w    = (const float*)d_in[14];
    const float* n2b    = (const float*)d_in[15];
    const float* fc1_w  = (const float*)d_in[16];
    const float* fc1_b  = (const float*)d_in[17];
    const float* fc2_w  = (const float*)d_in[18];
    const float* fc2_b  = (const float*)d_in[19];
    float* out = (float*)d_out;

    float *xall, *qb, *kvb, *h1, *offs, *att, *xres, *xn2, *hid, *wr, *st1, *st2;
    cudaGetSymbolAddress((void**)&xall, g_xall);
    cudaGetSymbolAddress((void**)&qb,   g_q);
    cudaGetSymbolAddress((void**)&kvb,  g_kv);
    cudaGetSymbolAddress((void**)&h1,   g_h1);
    cudaGetSymbolAddress((void**)&offs, g_offs);
    cudaGetSymbolAddress((void**)&att,  g_att);
    cudaGetSymbolAddress((void**)&xres, g_xres);
    cudaGetSymbolAddress((void**)&xn2,  g_xn2);
    cudaGetSymbolAddress((void**)&hid,  g_hid);
    cudaGetSymbolAddress((void**)&wr,   g_wr);
    cudaGetSymbolAddress((void**)&st1,  g_st1);
    cudaGetSymbolAddress((void**)&st2,  g_st2);

    // 1. repack conv weights
    repack_k<<<4608, 256>>>(off1_w, wr);
    // 2. gn1 stats (x_q and x_kv, 4 batches each)
    gn_stats_k<<<8, 512>>>(x_q, x_kv, st1);
    // 3. normalize + transpose to NHWC (both tensors)
    norm_pack_k<<<dim3(128, 8, 8), dim3(32, 8)>>>(x_q, x_kv, st1, n1w, n1b, xall);
    // 4. q = (xq_n @ q_w^T + b) * ch^-0.5
    gemm_k<1, false><<<dim3(4, 256), 256>>>(xall, q_w, q_b, qb, 256, 256, 512,
                                            nullptr, 0.17677669529663689f);
    // 5. kv = xkv_n @ kv_w^T + b
    gemm_k<0, false><<<dim3(8, 256), 256>>>(xall + 256, kv_w, kv_b, kvb, 512, 256, 512,
                                            nullptr, 0.f);
    // 6. h1 = relu(conv3x3([xq_n|xkv_n]))   (implicit im2col, K=4608)
    gemm_k<2, true><<<dim3(4, 256), 256>>>(xall, wr, off1_b, h1, 256, 4608, 0, nullptr, 0.f);
    // 7. offsets = h1 @ off2_w^T + b
    off2_k<<<(MTOT * 18) / 256, 256>>>(h1, off2_w, off2_b, offs);
    // 8. fused bilinear-sample + attention
    attn_k<<<2048, 256>>>(qb, kvb, offs, att);
    // 9. xres = x_q + att @ proj_w^T + b
    gemm_k<4, false><<<dim3(4, 256), 256>>>(att, proj_w, proj_b, xres, 256, 256, 256,
                                            x_q, 0.f);
    // 10. gn2 stats
    gn_stats_k<<<4, 512>>>(xres, xres, st2);
    // 11. normalize2
    norm2_k<<<(MTOT * 256) / 256, 256>>>(xres, st2, n2w, n2b, xn2);
    // 12. hid = gelu(xn2 @ fc1_w^T + b)
    gemm_k<3, false><<<dim3(16, 256), 256>>>(xn2, fc1_w, fc1_b, hid, 1024, 256, 256,
                                             nullptr, 0.f);
    // 13. out(NCHW) = xres + hid @ fc2_w^T + b
    gemm_k<5, false><<<dim3(4, 256), 256>>>(hid, fc2_w, fc2_b, out, 256, 1024, 1024,
                                            xres, 0.f);
}

// round 2
// speedup vs baseline: 2.1186x; 2.1186x over previous
#include <cuda_runtime.h>
#include <math.h>
#include <stdint.h>

// ---------------- problem constants ----------------
#define NB    4
#define SP    4096
#define MTOT  16384

// ---------------- scratch ----------------
__device__ float g_xall[(size_t)MTOT * 512];
__device__ float g_q   [(size_t)MTOT * 256];
__device__ float g_kv  [(size_t)MTOT * 512];
__device__ float g_h1  [(size_t)MTOT * 256];
__device__ float g_offs[(size_t)MTOT * 18];
__device__ float g_att [(size_t)MTOT * 256];
__device__ float g_xres[(size_t)MTOT * 256];
__device__ float g_xn2 [(size_t)MTOT * 256];
__device__ float g_hid [(size_t)MTOT * 1024];
__device__ float g_wr  [256 * 4608];
__device__ float g_st1 [16];
__device__ float g_st2 [8];

// ---------------- conv weight repack ----------------
__global__ void repack_k(const float* __restrict__ w, float* __restrict__ wr) {
    int id = blockIdx.x * blockDim.x + threadIdx.x;
    if (id >= 256 * 4608) return;
    int o = id / 4608, k = id - o * 4608;
    int nb = k >> 9, c = k & 511;
    int ky = nb / 3, kx = nb - ky * 3;
    wr[id] = w[((size_t)o * 512 + c) * 9 + ky * 3 + kx];
}

// ---------------- groupnorm stats ----------------
__global__ void gn_stats_k(const float* __restrict__ A, const float* __restrict__ Bsrc,
                           float* __restrict__ stats) {
    int bi = blockIdx.x;
    int tensor = bi >> 2, batch = bi & 3;
    const float* src = (tensor == 0 ? A : Bsrc) + ((size_t)batch << 20);
    const float4* p4 = reinterpret_cast<const float4*>(src);
    float s = 0.f, s2 = 0.f;
    for (int i = threadIdx.x; i < (1 << 18); i += blockDim.x) {
        float4 v = p4[i];
        s  += v.x + v.y + v.z + v.w;
        s2 += v.x * v.x + v.y * v.y + v.z * v.z + v.w * v.w;
    }
    __shared__ float sh1[512], sh2[512];
    sh1[threadIdx.x] = s; sh2[threadIdx.x] = s2;
    __syncthreads();
    for (int st = 256; st > 0; st >>= 1) {
        if (threadIdx.x < st) { sh1[threadIdx.x] += sh1[threadIdx.x + st];
                                sh2[threadIdx.x] += sh2[threadIdx.x + st]; }
        __syncthreads();
    }
    if (threadIdx.x == 0) {
        float inv = 1.f / 1048576.f;
        float mu = sh1[0] * inv;
        float var = sh2[0] * inv - mu * mu;
        stats[bi * 2] = mu;
        stats[bi * 2 + 1] = rsqrtf(var + 1e-5f);
    }
}

// ---------------- normalize + NCHW->NHWC pack ----------------
__global__ void norm_pack_k(const float* __restrict__ xq, const float* __restrict__ xkv,
                            const float* __restrict__ stats, const float* __restrict__ w,
                            const float* __restrict__ bb, float* __restrict__ xall) {
    __shared__ float tile[32][33];
    int bz = blockIdx.z;
    int tensor = bz >> 2, batch = bz & 3;
    const float* src = (tensor == 0 ? xq : xkv) + ((size_t)batch << 20);
    float mu = stats[bz * 2], rstd = stats[bz * 2 + 1];
    int s0 = blockIdx.x * 32, c0 = blockIdx.y * 32;
    int tx = threadIdx.x, ty = threadIdx.y;
#pragma unroll
    for (int k = 0; k < 4; k++) {
        int c = c0 + ty + k * 8;
        tile[ty + k * 8][tx] = src[(size_t)c * 4096 + s0 + tx];
    }
    __syncthreads();
#pragma unroll
    for (int k = 0; k < 4; k++) {
        int sl = ty + k * 8;
        int c = c0 + tx;
        float v = (tile[tx][sl] - mu) * rstd * w[c] + bb[c];
        xall[(((size_t)batch * 4096 + s0 + sl) << 9) + tensor * 256 + c] = v;
    }
}

// ---------------- norm2 ----------------
__global__ void norm2_k(const float* __restrict__ xres, const float* __restrict__ stats,
                        const float* __restrict__ w, const float* __restrict__ bb,
                        float* __restrict__ xn) {
    int id = blockIdx.x * blockDim.x + threadIdx.x;
    if (id >= MTOT * 256) return;
    int b = id >> 20, c = id & 255;
    xn[id] = (xres[id] - stats[b * 2]) * stats[b * 2 + 1] * w[c] + bb[c];
}

// ---------------- tf32 helpers ----------------
__device__ __forceinline__ float to_tf32(float x) {
    uint32_t u;
    asm("cvt.rna.tf32.f32 %0, %1;" : "=r"(u) : "f"(x));
    return __uint_as_float(u);
}
__device__ __forceinline__ void mma8(float4& d, const uint32_t* a, const uint32_t* b) {
    asm volatile("mma.sync.aligned.m16n8k8.row.col.f32.tf32.tf32.f32 "
        "{%0,%1,%2,%3}, {%4,%5,%6,%7}, {%8,%9}, {%0,%1,%2,%3};\n"
        : "+f"(d.x), "+f"(d.y), "+f"(d.z), "+f"(d.w)
        : "r"(a[0]), "r"(a[1]), "r"(a[2]), "r"(a[3]), "r"(b[0]), "r"(b[1]));
}

// ---------------- tensor-core GEMM: C[M,N] = A[M,K] @ W[N,K]^T + bias ----------------
// MODE 0: plain  1: *scale  2: relu  3: gelu
// MODE 4: +residual(NCHW R), store NHWC    MODE 5: +residual(NHWC R), store NCHW
// Tiles: 128x128x32, 256 threads (8 warps, 2Mx4N), warp 64x32, mma m16n8k8 tf32.
// Smem: k-major with XOR swizzle col^(((k>>2)&7)<<2), row stride 136 floats.
template <int MODE, bool IM2COL>
__global__ void __launch_bounds__(256) gemm_tc(
    const float* __restrict__ A, const float* __restrict__ W,
    const float* __restrict__ bias, float* __restrict__ C,
    int N, int K, int lda, const float* __restrict__ R, float scale)
{
    extern __shared__ float smbuf[];
    float* Asm = smbuf;          // [2][32][136]
    float* Bsm = smbuf + 8704;   // [2][32][136]

    const int tid  = threadIdx.x;
    const int bm   = blockIdx.y << 7, bn = blockIdx.x << 7;
    const int warp = tid >> 5, lane = tid & 31;
    const int wm   = (warp >> 2) << 6, wn = (warp & 3) << 5;
    const int la3  = lane & 3, lg = lane >> 2;

    const int lm  = tid >> 3;            // 0..31 (+32*i)
    const int lk  = (tid & 7) << 2;      // 0,4,...,28
    const int swz = (tid & 7) << 2;      // store xor = ((lk+j)>>2 & 7)<<2

    float4 pa[4], pb[4];
    float4 acc[4][4];
#pragma unroll
    for (int i = 0; i < 4; i++)
#pragma unroll
        for (int j = 0; j < 4; j++) acc[i][j] = make_float4(0.f, 0.f, 0.f, 0.f);

    const int nkb = K >> 5;

#define LDG_TILE(K0)                                                              \
    {                                                                             \
        _Pragma("unroll")                                                         \
        for (int i = 0; i < 4; i++) {                                             \
            const int m = lm + (i << 5);                                          \
            if (!IM2COL) {                                                        \
                pa[i] = *(const float4*)(A + (size_t)(bm + m) * lda + (K0) + lk); \
            } else {                                                              \
                const int gm = bm + m;                                            \
                const int ib = gm >> 12, sp_ = gm & 4095;                         \
                const int iy = sp_ >> 6, ix = sp_ & 63;                           \
                const int kk = (K0) + lk;                                         \
                const int nb = kk >> 9, cc = kk & 511;                            \
                const int qy = nb / 3;                                            \
                const int yy = iy + qy - 1, xx = ix + (nb - qy * 3) - 1;          \
                if (yy >= 0 && yy < 64 && xx >= 0 && xx < 64)                     \
                    pa[i] = *(const float4*)(A + (((size_t)ib * 4096 + yy * 64 + xx) << 9) + cc); \
                else                                                              \
                    pa[i] = make_float4(0.f, 0.f, 0.f, 0.f);                      \
            }                                                                     \
            pb[i] = *(const float4*)(W + (size_t)(bn + m) * (size_t)K + (K0) + lk); \
        }                                                                         \
    }

#define STS_TILE(BUF)                                                             \
    {                                                                             \
        float* ab = Asm + (BUF) * 4352 + lk * 136;                                \
        float* bb = Bsm + (BUF) * 4352 + lk * 136;                                \
        _Pragma("unroll")                                                         \
        for (int i = 0; i < 4; i++) {                                             \
            const int col = (lm + (i << 5)) ^ swz;                                \
            ab[col]       = to_tf32(pa[i].x);                                     \
            ab[136 + col] = to_tf32(pa[i].y);                                     \
            ab[272 + col] = to_tf32(pa[i].z);                                     \
            ab[408 + col] = to_tf32(pa[i].w);                                     \
            bb[col]       = to_tf32(pb[i].x);                                     \
            bb[136 + col] = to_tf32(pb[i].y);                                     \
            bb[272 + col] = to_tf32(pb[i].z);                                     \
            bb[408 + col] = to_tf32(pb[i].w);                                     \
        }                                                                         \
    }

    LDG_TILE(0);
    STS_TILE(0);
    __syncthreads();

    int buf = 0;
    for (int kb = 0; kb < nkb; kb++) {
        const bool more = (kb + 1 < nkb);
        if (more) LDG_TILE((kb + 1) << 5);

        const float* Ab = Asm + buf * 4352;
        const float* Bb = Bsm + buf * 4352;
#pragma unroll
        for (int ks = 0; ks < 4; ks++) {
            const int r0 = (ks * 8 + la3) * 136;
            const int r1 = (ks * 8 + 4 + la3) * 136;
            const int C0 = ((2 * ks) & 7) << 2;
            const int C1 = ((2 * ks + 1) & 7) << 2;
            uint32_t af[4][4], bf[4][2];
#pragma unroll
            for (int mt = 0; mt < 4; mt++) {
                const int m = wm + (mt << 4) + lg;
                af[mt][0] = __float_as_uint(Ab[r0 + (m ^ C0)]);
                af[mt][1] = __float_as_uint(Ab[r0 + ((m + 8) ^ C0)]);
                af[mt][2] = __float_as_uint(Ab[r1 + (m ^ C1)]);
                af[mt][3] = __float_as_uint(Ab[r1 + ((m + 8) ^ C1)]);
            }
#pragma unroll
            for (int nt = 0; nt < 4; nt++) {
                const int n = wn + (nt << 3) + lg;
                bf[nt][0] = __float_as_uint(Bb[r0 + (n ^ C0)]);
                bf[nt][1] = __float_as_uint(Bb[r1 + (n ^ C1)]);
            }
#pragma unroll
            for (int mt = 0; mt < 4; mt++)
#pragma unroll
                for (int nt = 0; nt < 4; nt++)
                    mma8(acc[mt][nt], af[mt], bf[nt]);
        }
        if (more) { STS_TILE(buf ^ 1); __syncthreads(); buf ^= 1; }
    }

    // ---------------- epilogue ----------------
#pragma unroll
    for (int mt = 0; mt < 4; mt++) {
        const int m0 = bm + wm + (mt << 4) + lg;
#pragma unroll
        for (int nt = 0; nt < 4; nt++) {
            const int n = bn + wn + (nt << 3) + (la3 << 1);
            const float b0 = bias[n], b1 = bias[n + 1];
            float v[4] = {acc[mt][nt].x + b0, acc[mt][nt].y + b1,
                          acc[mt][nt].z + b0, acc[mt][nt].w + b1};
#pragma unroll
            for (int h = 0; h < 2; h++) {
                const int m = m0 + h * 8;
#pragma unroll
                for (int j = 0; j < 2; j++) {
                    float x = v[h * 2 + j];
                    const int nn = n + j;
                    if (MODE == 1) x *= scale;
                    if (MODE == 2) x = fmaxf(x, 0.f);
                    if (MODE == 3) x = 0.5f * x * (1.f + erff(x * 0.70710678118654752f));
                    if (MODE == 4) x += R[((size_t)(m >> 12) * 256 + nn) * 4096 + (m & 4095)];
                    if (MODE == 5) x += R[(size_t)m * 256 + nn];
                    if (MODE == 5)
                        C[((size_t)(m >> 12) * 256 + nn) * 4096 + (m & 4095)] = x;
                    else
                        C[(size_t)m * (size_t)N + nn] = x;
                }
            }
        }
    }
#undef LDG_TILE
#undef STS_TILE
}

// ---------------- offset head ----------------
__global__ void off2_k(const float* __restrict__ h1, const float* __restrict__ w,
                       const float* __restrict__ bias, float* __restrict__ offs) {
    int id = blockIdx.x * blockDim.x + threadIdx.x;
    if (id >= MTOT * 18) return;
    int m = id / 18, n = id - m * 18;
    const float4* a = reinterpret_cast<const float4*>(h1 + (size_t)m * 256);
    const float4* ww = reinterpret_cast<const float4*>(w + (size_t)n * 256);
    float s = bias[n];
#pragma unroll 8
    for (int k = 0; k < 64; k++) {
        float4 av = a[k], wv = ww[k];
        s += av.x * wv.x + av.y * wv.y + av.z * wv.z + av.w * wv.w;
    }
    offs[id] = s;
}

// ---------------- fused bilinear-sample + 9-way attention ----------------
#define LOAD8(dst, ptr)                                                     \
    {                                                                       \
        float4 _u0 = *reinterpret_cast<const float4*>(ptr);                 \
        float4 _u1 = *reinterpret_cast<const float4*>((ptr) + 4);           \
        dst[0] = _u0.x; dst[1] = _u0.y; dst[2] = _u0.z; dst[3] = _u0.w;     \
        dst[4] = _u1.x; dst[5] = _u1.y; dst[6] = _u1.z; dst[7] = _u1.w;     \
    }

__global__ void __launch_bounds__(256) attn_k(
    const float* __restrict__ qb, const float* __restrict__ kv,
    const float* __restrict__ offs, float* __restrict__ outp) {
    __shared__ float sh[8][9][8];
    const int warp = threadIdx.x >> 5, lane = threadIdx.x & 31;
    const int p = blockIdx.x * 8 + warp;
    const int b = p >> 12, s = p & 4095, y = s >> 6, x = s & 63;
    const float* kvb = kv + (((size_t)b << 12) << 9);

    float qr[8];
    LOAD8(qr, qb + (size_t)p * 256 + lane * 8);

    for (int o = 0; o < 9; o++) {
        int ys = y + o / 3 - 1, xs = x + o % 3 - 1;
        float prod[8] = {0.f, 0.f, 0.f, 0.f, 0.f, 0.f, 0.f, 0.f};
        if (ys >= 0 && ys < 64 && xs >= 0 && xs < 64) {
            const float* op = offs + (size_t)((b << 12) + (ys << 6) + xs) * 18 + 2 * o;
            float px = op[0], py = op[1];
            float y0f = floorf(py), x0f = floorf(px);
            float wy = py - y0f, wx = px - x0f;
            int y0 = (int)y0f, x0 = (int)x0f;
            float w00 = (1.f - wy) * (1.f - wx), w01 = (1.f - wy) * wx;
            float w10 = wy * (1.f - wx), w11 = wy * wx;
            bool vy0 = (y0 >= 0) && (y0 < 64), vy1 = (y0 + 1 >= 0) && (y0 + 1 < 64);
            bool vx0 = (x0 >= 0) && (x0 < 64), vx1 = (x0 + 1 >= 0) && (x0 + 1 < 64);
            w00 = (vy0 && vx0) ? w00 : 0.f; w01 = (vy0 && vx1) ? w01 : 0.f;
            w10 = (vy1 && vx0) ? w10 : 0.f; w11 = (vy1 && vx1) ? w11 : 0.f;
            int y0c = min(max(y0, 0), 63), y1c = min(max(y0 + 1, 0), 63);
            int x0c = min(max(x0, 0), 63), x1c = min(max(x0 + 1, 0), 63);
            float c00[8], c01[8], c10[8], c11[8];
            LOAD8(c00, kvb + ((size_t)((y0c << 6) + x0c) << 9) + lane * 8);
            LOAD8(c01, kvb + ((size_t)((y0c << 6) + x1c) << 9) + lane * 8);
            LOAD8(c10, kvb + ((size_t)((y1c << 6) + x0c) << 9) + lane * 8);
            LOAD8(c11, kvb + ((size_t)((y1c << 6) + x1c) << 9) + lane * 8);
#pragma unroll
            for (int h = 0; h < 8; h++) {
                float kvv = w00 * c00[h] + w01 * c01[h] + w10 * c10[h] + w11 * c11[h];
                prod[h] = qr[h] * kvv;
            }
        }
#pragma unroll
        for (int off = 16; off > 0; off >>= 1)
#pragma unroll
            for (int h = 0; h < 8; h++)
                prod[h] += __shfl_xor_sync(0xffffffffu, prod[h], off);
        if (lane == 0) {
#pragma unroll
            for (int h = 0; h < 8; h++) sh[warp][o][h] = prod[h];
        }
    }
    __syncwarp();
    if (lane < 8) {
        float e[9]; float mx = -1e30f;
#pragma unroll
        for (int o = 0; o < 9; o++) { e[o] = sh[warp][o][lane]; mx = fmaxf(mx, e[o]); }
        float sm = 0.f;
#pragma unroll
        for (int o = 0; o < 9; o++) { e[o] = expf(e[o] - mx); sm += e[o]; }
        float inv = 1.f / sm;
#pragma unroll
        for (int o = 0; o < 9; o++) sh[warp][o][lane] = e[o] * inv;
    }
    __syncwarp();
    float acc[8] = {0.f, 0.f, 0.f, 0.f, 0.f, 0.f, 0.f, 0.f};
    for (int o = 0; o < 9; o++) {
        int ys = y + o / 3 - 1, xs = x + o % 3 - 1;
        if (ys < 0 || ys >= 64 || xs < 0 || xs >= 64) continue;
        const float* op = offs + (size_t)((b << 12) + (ys << 6) + xs) * 18 + 2 * o;
        float px = op[0], py = op[1];
        float y0f = floorf(py), x0f = floorf(px);
        float wy = py - y0f, wx = px - x0f;
        int y0 = (int)y0f, x0 = (int)x0f;
        float w00 = (1.f - wy) * (1.f - wx), w01 = (1.f - wy) * wx;
        float w10 = wy * (1.f - wx), w11 = wy * wx;
        bool vy0 = (y0 >= 0) && (y0 < 64), vy1 = (y0 + 1 >= 0) && (y0 + 1 < 64);
        bool vx0 = (x0 >= 0) && (x0 < 64), vx1 = (x0 + 1 >= 0) && (x0 + 1 < 64);
        w00 = (vy0 && vx0) ? w00 : 0.f; w01 = (vy0 && vx1) ? w01 : 0.f;
        w10 = (vy1 && vx0) ? w10 : 0.f; w11 = (vy1 && vx1) ? w11 : 0.f;
        int y0c = min(max(y0, 0), 63), y1c = min(max(y0 + 1, 0), 63);
        int x0c = min(max(x0, 0), 63), x1c = min(max(x0 + 1, 0), 63);
        float c00[8], c01[8], c10[8], c11[8];
        LOAD8(c00, kvb + ((size_t)((y0c << 6) + x0c) << 9) + 256 + lane * 8);
        LOAD8(c01, kvb + ((size_t)((y0c << 6) + x1c) << 9) + 256 + lane * 8);
        LOAD8(c10, kvb + ((size_t)((y1c << 6) + x0c) << 9) + 256 + lane * 8);
        LOAD8(c11, kvb + ((size_t)((y1c << 6) + x1c) << 9) + 256 + lane * 8);
#pragma unroll
        for (int h = 0; h < 8; h++) {
            float vv = w00 * c00[h] + w01 * c01[h] + w10 * c10[h] + w11 * c11[h];
            acc[h] += sh[warp][o][h] * vv;
        }
    }
    float4* po = reinterpret_cast<float4*>(outp + (size_t)p * 256 + lane * 8);
    po[0] = make_float4(acc[0], acc[1], acc[2], acc[3]);
    po[1] = make_float4(acc[4], acc[5], acc[6], acc[7]);
}

// ---------------- host ----------------
extern "C" void kernel_launch(void* const* d_in, const int* in_sizes, int n_in,
                              void* d_out, int out_size) {
    const float* x_q    = (const float*)d_in[0];
    const float* x_kv   = (const float*)d_in[1];
    const float* n1w    = (const float*)d_in[2];
    const float* n1b    = (const float*)d_in[3];
    const float* q_w    = (const float*)d_in[4];
    const float* q_b    = (const float*)d_in[5];
    const float* kv_w   = (const float*)d_in[6];
    const float* kv_b   = (const float*)d_in[7];
    const float* off1_w = (const float*)d_in[8];
    const float* off1_b = (const float*)d_in[9];
    const float* off2_w = (const float*)d_in[10];
    const float* off2_b = (const float*)d_in[11];
    const float* proj_w = (const float*)d_in[12];
    const float* proj_b = (const float*)d_in[13];
    const float* n2w    = (const float*)d_in[14];
    const float* n2b    = (const float*)d_in[15];
    const float* fc1_w  = (const float*)d_in[16];
    const float* fc1_b  = (const float*)d_in[17];
    const float* fc2_w  = (const float*)d_in[18];
    const float* fc2_b  = (const float*)d_in[19];
    float* out = (float*)d_out;

    float *xall, *qb, *kvb, *h1, *offs, *att, *xres, *xn2, *hid, *wr, *st1, *st2;
    cudaGetSymbolAddress((void**)&xall, g_xall);
    cudaGetSymbolAddress((void**)&qb,   g_q);
    cudaGetSymbolAddress((void**)&kvb,  g_kv);
    cudaGetSymbolAddress((void**)&h1,   g_h1);
    cudaGetSymbolAddress((void**)&offs, g_offs);
    cudaGetSymbolAddress((void**)&att,  g_att);
    cudaGetSymbolAddress((void**)&xres, g_xres);
    cudaGetSymbolAddress((void**)&xn2,  g_xn2);
    cudaGetSymbolAddress((void**)&hid,  g_hid);
    cudaGetSymbolAddress((void**)&wr,   g_wr);
    cudaGetSymbolAddress((void**)&st1,  g_st1);
    cudaGetSymbolAddress((void**)&st2,  g_st2);

    const int SMEM = 69632;
    cudaFuncSetAttribute(gemm_tc<1, false>, cudaFuncAttributeMaxDynamicSharedMemorySize, SMEM);
    cudaFuncSetAttribute(gemm_tc<0, false>, cudaFuncAttributeMaxDynamicSharedMemorySize, SMEM);
    cudaFuncSetAttribute(gemm_tc<2, true >, cudaFuncAttributeMaxDynamicSharedMemorySize, SMEM);
    cudaFuncSetAttribute(gemm_tc<4, false>, cudaFuncAttributeMaxDynamicSharedMemorySize, SMEM);
    cudaFuncSetAttribute(gemm_tc<3, false>, cudaFuncAttributeMaxDynamicSharedMemorySize, SMEM);
    cudaFuncSetAttribute(gemm_tc<5, false>, cudaFuncAttributeMaxDynamicSharedMemorySize, SMEM);

    repack_k<<<4608, 256>>>(off1_w, wr);
    gn_stats_k<<<8, 512>>>(x_q, x_kv, st1);
    norm_pack_k<<<dim3(128, 8, 8), dim3(32, 8)>>>(x_q, x_kv, st1, n1w, n1b, xall);

    // q = (xq_n @ q_w^T + b) * ch^-0.5
    gemm_tc<1, false><<<dim3(2, 128), 256, SMEM>>>(xall, q_w, q_b, qb, 256, 256, 512,
                                                   nullptr, 0.17677669529663689f);
    // kv = xkv_n @ kv_w^T + b
    gemm_tc<0, false><<<dim3(4, 128), 256, SMEM>>>(xall + 256, kv_w, kv_b, kvb, 512, 256, 512,
                                                   nullptr, 0.f);
    // h1 = relu(conv3x3([xq_n|xkv_n]))
    gemm_tc<2, true ><<<dim3(2, 128), 256, SMEM>>>(xall, wr, off1_b, h1, 256, 4608, 0,
                                                   nullptr, 0.f);
    off2_k<<<(MTOT * 18) / 256, 256>>>(h1, off2_w, off2_b, offs);
    attn_k<<<2048, 256>>>(qb, kvb, offs, att);
    // xres = x_q + att @ proj_w^T + b
    gemm_tc<4, false><<<dim3(2, 128), 256, SMEM>>>(att, proj_w, proj_b, xres, 256, 256, 256,
                                                   x_q, 0.f);
    gn_stats_k<<<4, 512>>>(xres, xres, st2);
    norm2_k<<<(MTOT * 256) / 256, 256>>>(xres, st2, n2w, n2b, xn2);
    // hid = gelu(xn2 @ fc1_w^T + b)
    gemm_tc<3, false><<<dim3(8, 128), 256, SMEM>>>(xn2, fc1_w, fc1_b, hid, 1024, 256, 256,
                                                   nullptr, 0.f);
    // out(NCHW) = xres + hid @ fc2_w^T + b
    gemm_tc<5, false><<<dim3(2, 128), 256, SMEM>>>(hid, fc2_w, fc2_b, out, 256, 1024, 1024,
                                                   xres, 0.f);
}

// round 3
// speedup vs baseline: 2.8796x; 1.3592x over previous
#include <cuda_runtime.h>
#include <math.h>
#include <stdint.h>

#define NB    4
#define SP    4096
#define MTOT  16384

// ---------------- scratch ----------------
__device__ float g_xall[(size_t)MTOT * 512];
__device__ float g_q   [(size_t)MTOT * 256];
__device__ float g_kv  [(size_t)MTOT * 512];
__device__ float g_h1  [(size_t)MTOT * 256];
__device__ float g_offs[(size_t)MTOT * 18];
__device__ float g_att [(size_t)MTOT * 256];
__device__ float g_xres[(size_t)MTOT * 256];
__device__ float g_xn2 [(size_t)MTOT * 256];
__device__ float g_hid [(size_t)MTOT * 1024];
__device__ float g_wr  [256 * 4608];
__device__ float g_st1 [16];
__device__ float g_st2 [8];

// ---------------- conv weight repack ----------------
__global__ void repack_k(const float* __restrict__ w, float* __restrict__ wr) {
    int id = blockIdx.x * blockDim.x + threadIdx.x;
    if (id >= 256 * 4608) return;
    int o = id / 4608, k = id - o * 4608;
    int nb = k >> 9, c = k & 511;
    int ky = nb / 3, kx = nb - ky * 3;
    wr[id] = w[((size_t)o * 512 + c) * 9 + ky * 3 + kx];
}

// ---------------- groupnorm stats ----------------
__global__ void gn_stats_k(const float* __restrict__ A, const float* __restrict__ Bsrc,
                           float* __restrict__ stats) {
    int bi = blockIdx.x;
    int tensor = bi >> 2, batch = bi & 3;
    const float* src = (tensor == 0 ? A : Bsrc) + ((size_t)batch << 20);
    const float4* p4 = reinterpret_cast<const float4*>(src);
    float s = 0.f, s2 = 0.f;
    for (int i = threadIdx.x; i < (1 << 18); i += blockDim.x) {
        float4 v = p4[i];
        s  += v.x + v.y + v.z + v.w;
        s2 += v.x * v.x + v.y * v.y + v.z * v.z + v.w * v.w;
    }
    __shared__ float sh1[512], sh2[512];
    sh1[threadIdx.x] = s; sh2[threadIdx.x] = s2;
    __syncthreads();
    for (int st = 256; st > 0; st >>= 1) {
        if (threadIdx.x < st) { sh1[threadIdx.x] += sh1[threadIdx.x + st];
                                sh2[threadIdx.x] += sh2[threadIdx.x + st]; }
        __syncthreads();
    }
    if (threadIdx.x == 0) {
        float inv = 1.f / 1048576.f;
        float mu = sh1[0] * inv;
        float var = sh2[0] * inv - mu * mu;
        stats[bi * 2] = mu;
        stats[bi * 2 + 1] = rsqrtf(var + 1e-5f);
    }
}

// ---------------- normalize + NCHW->NHWC pack ----------------
__global__ void norm_pack_k(const float* __restrict__ xq, const float* __restrict__ xkv,
                            const float* __restrict__ stats, const float* __restrict__ w,
                            const float* __restrict__ bb, float* __restrict__ xall) {
    __shared__ float tile[32][33];
    int bz = blockIdx.z;
    int tensor = bz >> 2, batch = bz & 3;
    const float* src = (tensor == 0 ? xq : xkv) + ((size_t)batch << 20);
    float mu = stats[bz * 2], rstd = stats[bz * 2 + 1];
    int s0 = blockIdx.x * 32, c0 = blockIdx.y * 32;
    int tx = threadIdx.x, ty = threadIdx.y;
#pragma unroll
    for (int k = 0; k < 4; k++) {
        int c = c0 + ty + k * 8;
        tile[ty + k * 8][tx] = src[(size_t)c * 4096 + s0 + tx];
    }
    __syncthreads();
#pragma unroll
    for (int k = 0; k < 4; k++) {
        int sl = ty + k * 8;
        int c = c0 + tx;
        float v = (tile[tx][sl] - mu) * rstd * w[c] + bb[c];
        xall[(((size_t)batch * 4096 + s0 + sl) << 9) + tensor * 256 + c] = v;
    }
}

// ---------------- norm2 ----------------
__global__ void norm2_k(const float* __restrict__ xres, const float* __restrict__ stats,
                        const float* __restrict__ w, const float* __restrict__ bb,
                        float* __restrict__ xn) {
    int id = blockIdx.x * blockDim.x + threadIdx.x;
    if (id >= MTOT * 256) return;
    int b = id >> 20, c = id & 255;
    xn[id] = (xres[id] - stats[b * 2]) * stats[b * 2 + 1] * w[c] + bb[c];
}

// ---------------- PTX helpers ----------------
__device__ __forceinline__ void mma8(float4& d, const uint32_t* a, const uint32_t* b) {
    asm volatile("mma.sync.aligned.m16n8k8.row.col.f32.tf32.tf32.f32 "
        "{%0,%1,%2,%3}, {%4,%5,%6,%7}, {%8,%9}, {%0,%1,%2,%3};\n"
        : "+f"(d.x), "+f"(d.y), "+f"(d.z), "+f"(d.w)
        : "r"(a[0]), "r"(a[1]), "r"(a[2]), "r"(a[3]), "r"(b[0]), "r"(b[1]));
}
__device__ __forceinline__ void ldsm4(uint32_t* r, uint32_t a) {
    asm volatile("ldmatrix.sync.aligned.m8n8.x4.shared.b16 {%0,%1,%2,%3}, [%4];"
        : "=r"(r[0]), "=r"(r[1]), "=r"(r[2]), "=r"(r[3]) : "r"(a));
}
__device__ __forceinline__ void ldsm2(uint32_t* r, uint32_t a) {
    asm volatile("ldmatrix.sync.aligned.m8n8.x2.shared.b16 {%0,%1}, [%2];"
        : "=r"(r[0]), "=r"(r[1]) : "r"(a));
}
__device__ __forceinline__ void cp16(uint32_t d, const void* s, int sz) {
    asm volatile("cp.async.cg.shared.global [%0], [%1], 16, %2;"
        :: "r"(d), "l"(s), "r"(sz));
}
#define CP_COMMIT() asm volatile("cp.async.commit_group;")
template <int N>
__device__ __forceinline__ void cp_wait() {
    asm volatile("cp.async.wait_group %0;" :: "n"(N));
}

// ---------------- async-pipelined tf32 tensor-core GEMM ----------------
// C[M,N] = A[M,K] @ W[N,K]^T + bias.
// Tiles 128x128x32, 256 thr (8 warps 2Mx4N), 3-stage cp.async, ldmatrix fragments.
// Smem per stage: A[128][32] + B[128][32] floats (k-contiguous rows of 128B),
// 16B-chunk swizzle c ^ (row&7). Stage = 32KB, total 96KB.
// MODE 0 plain / 1 *scale / 2 relu / 3 gelu / 4 +R(NCHW)->NHWC / 5 +R(NHWC)->NCHW
#define STG_BYTES 32768

template <bool IM2COL>
__device__ __forceinline__ void issue_tile(
    uint32_t sa, const float* __restrict__ A, const float* __restrict__ W,
    int bm, int bn, int K0, int lda, int K, int lrow, int lc, uint32_t swz)
{
#pragma unroll
    for (int i = 0; i < 4; i++) {
        const int row = lrow + (i << 5);
        const float* srcA;
        int sz = 16;
        if (!IM2COL) {
            srcA = A + (size_t)(bm + row) * lda + K0 + lc * 4;
        } else {
            const int gm = bm + row;
            const int ib = gm >> 12, sp = gm & 4095;
            const int iy = sp >> 6, ix = sp & 63;
            const int nb = K0 >> 9, cc0 = K0 & 511;
            const int qy = nb / 3;
            const int yy = iy + qy - 1, xx = ix + (nb - qy * 3) - 1;
            srcA = A + (((size_t)(ib << 12) + (yy << 6) + xx) << 9) + cc0 + lc * 4;
            if (!(yy >= 0 && yy < 64 && xx >= 0 && xx < 64)) { sz = 0; srcA = A; }
        }
        cp16(sa + row * 128 + swz, srcA, sz);
        cp16(sa + 16384 + row * 128 + swz,
             W + (size_t)(bn + row) * (size_t)K + K0 + lc * 4, 16);
    }
}

template <int MODE, bool IM2COL>
__global__ void __launch_bounds__(256, 2) gemm_tc(
    const float* __restrict__ A, const float* __restrict__ W,
    const float* __restrict__ bias, float* __restrict__ C,
    int N, int K, int lda, const float* __restrict__ R, float scale)
{
    extern __shared__ float smbuf[];
    const uint32_t smem_base = (uint32_t)__cvta_generic_to_shared(smbuf);

    const int tid  = threadIdx.x;
    const int bm   = blockIdx.y << 7, bn = blockIdx.x << 7;
    const int warp = tid >> 5, lane = tid & 31;
    const int wm   = (warp >> 2) << 6, wn = (warp & 3) << 5;
    const int lg   = lane >> 2, la3 = lane & 3;

    // loader mapping
    const int lrow = tid >> 3, lc = tid & 7;
    const uint32_t swz = (uint32_t)((lc ^ (lrow & 7)) << 4);

    // ldmatrix per-lane constants
    const int l7 = lane & 7, lq = lane >> 3;
    uint32_t arow[4], brow[4];
#pragma unroll
    for (int mt = 0; mt < 4; mt++)
        arow[mt] = (uint32_t)((wm + mt * 16 + ((lq & 1) << 3) + l7) * 128);
    const int a_kq = lq >> 1;
#pragma unroll
    for (int nt = 0; nt < 4; nt++)
        brow[nt] = (uint32_t)(16384 + (wn + nt * 8 + l7) * 128);
    const int b_kq = lq & 1;

    float4 acc[4][4];
#pragma unroll
    for (int i = 0; i < 4; i++)
#pragma unroll
        for (int j = 0; j < 4; j++) acc[i][j] = make_float4(0.f, 0.f, 0.f, 0.f);

    const int nkb = K >> 5;
    issue_tile<IM2COL>(smem_base,             A, W, bm, bn,  0, lda, K, lrow, lc, swz);
    CP_COMMIT();
    issue_tile<IM2COL>(smem_base + STG_BYTES, A, W, bm, bn, 32, lda, K, lrow, lc, swz);
    CP_COMMIT();

    int stg = 0;
    for (int kb = 0; kb < nkb; kb++) {
        cp_wait<1>();
        __syncthreads();
        if (kb + 2 < nkb) {
            int s2 = stg + 2; if (s2 >= 3) s2 -= 3;
            issue_tile<IM2COL>(smem_base + s2 * STG_BYTES, A, W, bm, bn,
                               (kb + 2) << 5, lda, K, lrow, lc, swz);
        }
        CP_COMMIT();

        const uint32_t Ab = smem_base + stg * STG_BYTES;
#pragma unroll
        for (int ks = 0; ks < 4; ks++) {
            const uint32_t axor = (uint32_t)((((ks << 1) + a_kq) ^ l7) << 4);
            const uint32_t bxor = (uint32_t)((((ks << 1) + b_kq) ^ l7) << 4);
            uint32_t af[4][4], bf[4][2];
#pragma unroll
            for (int mt = 0; mt < 4; mt++) ldsm4(af[mt], Ab + arow[mt] + axor);
#pragma unroll
            for (int nt = 0; nt < 4; nt++) ldsm2(bf[nt], Ab + brow[nt] + bxor);
#pragma unroll
            for (int mt = 0; mt < 4; mt++)
#pragma unroll
                for (int nt = 0; nt < 4; nt++)
                    mma8(acc[mt][nt], af[mt], bf[nt]);
        }
        if (++stg == 3) stg = 0;
    }

    // ---------------- epilogue ----------------
#pragma unroll
    for (int mt = 0; mt < 4; mt++) {
        const int m0 = bm + wm + (mt << 4) + lg;
#pragma unroll
        for (int nt = 0; nt < 4; nt++) {
            const int n = bn + wn + (nt << 3) + (la3 << 1);
            const float b0 = bias[n], b1 = bias[n + 1];
            float v[4] = {acc[mt][nt].x + b0, acc[mt][nt].y + b1,
                          acc[mt][nt].z + b0, acc[mt][nt].w + b1};
#pragma unroll
            for (int h = 0; h < 2; h++) {
                const int m = m0 + h * 8;
#pragma unroll
                for (int j = 0; j < 2; j++) {
                    float x = v[h * 2 + j];
                    const int nn = n + j;
                    if (MODE == 1) x *= scale;
                    if (MODE == 2) x = fmaxf(x, 0.f);
                    if (MODE == 3) x = 0.5f * x * (1.f + erff(x * 0.70710678118654752f));
                    if (MODE == 4) x += R[((size_t)(m >> 12) * 256 + nn) * 4096 + (m & 4095)];
                    if (MODE == 5) x += R[(size_t)m * 256 + nn];
                    if (MODE == 5)
                        C[((size_t)(m >> 12) * 256 + nn) * 4096 + (m & 4095)] = x;
                    else
                        C[(size_t)m * (size_t)N + nn] = x;
                }
            }
        }
    }
}

// ---------------- offset head ----------------
__global__ void off2_k(const float* __restrict__ h1, const float* __restrict__ w,
                       const float* __restrict__ bias, float* __restrict__ offs) {
    int id = blockIdx.x * blockDim.x + threadIdx.x;
    if (id >= MTOT * 18) return;
    int m = id / 18, n = id - m * 18;
    const float4* a = reinterpret_cast<const float4*>(h1 + (size_t)m * 256);
    const float4* ww = reinterpret_cast<const float4*>(w + (size_t)n * 256);
    float s = bias[n];
#pragma unroll 8
    for (int k = 0; k < 64; k++) {
        float4 av = a[k], wv = ww[k];
        s += av.x * wv.x + av.y * wv.y + av.z * wv.z + av.w * wv.w;
    }
    offs[id] = s;
}

// ---------------- fused bilinear-sample + 9-way attention ----------------
#define LOAD8(dst, ptr)                                                     \
    {                                                                       \
        float4 _u0 = *reinterpret_cast<const float4*>(ptr);                 \
        float4 _u1 = *reinterpret_cast<const float4*>((ptr) + 4);           \
        dst[0] = _u0.x; dst[1] = _u0.y; dst[2] = _u0.z; dst[3] = _u0.w;     \
        dst[4] = _u1.x; dst[5] = _u1.y; dst[6] = _u1.z; dst[7] = _u1.w;     \
    }

__global__ void __launch_bounds__(256) attn_k(
    const float* __restrict__ qb, const float* __restrict__ kv,
    const float* __restrict__ offs, float* __restrict__ outp) {
    __shared__ float sh[8][9][8];
    const int warp = threadIdx.x >> 5, lane = threadIdx.x & 31;
    const int p = blockIdx.x * 8 + warp;
    const int b = p >> 12, s = p & 4095, y = s >> 6, x = s & 63;
    const float* kvb = kv + (((size_t)b << 12) << 9);

    float qr[8];
    LOAD8(qr, qb + (size_t)p * 256 + lane * 8);

    for (int o = 0; o < 9; o++) {
        int ys = y + o / 3 - 1, xs = x + o % 3 - 1;
        float prod[8] = {0.f, 0.f, 0.f, 0.f, 0.f, 0.f, 0.f, 0.f};
        if (ys >= 0 && ys < 64 && xs >= 0 && xs < 64) {
            const float* op = offs + (size_t)((b << 12) + (ys << 6) + xs) * 18 + 2 * o;
            float px = op[0], py = op[1];
            float y0f = floorf(py), x0f = floorf(px);
            float wy = py - y0f, wx = px - x0f;
            int y0 = (int)y0f, x0 = (int)x0f;
            float w00 = (1.f - wy) * (1.f - wx), w01 = (1.f - wy) * wx;
            float w10 = wy * (1.f - wx), w11 = wy * wx;
            bool vy0 = (y0 >= 0) && (y0 < 64), vy1 = (y0 + 1 >= 0) && (y0 + 1 < 64);
            bool vx0 = (x0 >= 0) && (x0 < 64), vx1 = (x0 + 1 >= 0) && (x0 + 1 < 64);
            w00 = (vy0 && vx0) ? w00 : 0.f; w01 = (vy0 && vx1) ? w01 : 0.f;
            w10 = (vy1 && vx0) ? w10 : 0.f; w11 = (vy1 && vx1) ? w11 : 0.f;
            int y0c = min(max(y0, 0), 63), y1c = min(max(y0 + 1, 0), 63);
            int x0c = min(max(x0, 0), 63), x1c = min(max(x0 + 1, 0), 63);
            float c00[8], c01[8], c10[8], c11[8];
            LOAD8(c00, kvb + ((size_t)((y0c << 6) + x0c) << 9) + lane * 8);
            LOAD8(c01, kvb + ((size_t)((y0c << 6) + x1c) << 9) + lane * 8);
            LOAD8(c10, kvb + ((size_t)((y1c << 6) + x0c) << 9) + lane * 8);
            LOAD8(c11, kvb + ((size_t)((y1c << 6) + x1c) << 9) + lane * 8);
#pragma unroll
            for (int h = 0; h < 8; h++) {
                float kvv = w00 * c00[h] + w01 * c01[h] + w10 * c10[h] + w11 * c11[h];
                prod[h] = qr[h] * kvv;
            }
        }
#pragma unroll
        for (int off = 16; off > 0; off >>= 1)
#pragma unroll
            for (int h = 0; h < 8; h++)
                prod[h] += __shfl_xor_sync(0xffffffffu, prod[h], off);
        if (lane == 0) {
#pragma unroll
            for (int h = 0; h < 8; h++) sh[warp][o][h] = prod[h];
        }
    }
    __syncwarp();
    if (lane < 8) {
        float e[9]; float mx = -1e30f;
#pragma unroll
        for (int o = 0; o < 9; o++) { e[o] = sh[warp][o][lane]; mx = fmaxf(mx, e[o]); }
        float sm = 0.f;
#pragma unroll
        for (int o = 0; o < 9; o++) { e[o] = expf(e[o] - mx); sm += e[o]; }
        float inv = 1.f / sm;
#pragma unroll
        for (int o = 0; o < 9; o++) sh[warp][o][lane] = e[o] * inv;
    }
    __syncwarp();
    float acc[8] = {0.f, 0.f, 0.f, 0.f, 0.f, 0.f, 0.f, 0.f};
    for (int o = 0; o < 9; o++) {
        int ys = y + o / 3 - 1, xs = x + o % 3 - 1;
        if (ys < 0 || ys >= 64 || xs < 0 || xs >= 64) continue;
        const float* op = offs + (size_t)((b << 12) + (ys << 6) + xs) * 18 + 2 * o;
        float px = op[0], py = op[1];
        float y0f = floorf(py), x0f = floorf(px);
        float wy = py - y0f, wx = px - x0f;
        int y0 = (int)y0f, x0 = (int)x0f;
        float w00 = (1.f - wy) * (1.f - wx), w01 = (1.f - wy) * wx;
        float w10 = wy * (1.f - wx), w11 = wy * wx;
        bool vy0 = (y0 >= 0) && (y0 < 64), vy1 = (y0 + 1 >= 0) && (y0 + 1 < 64);
        bool vx0 = (x0 >= 0) && (x0 < 64), vx1 = (x0 + 1 >= 0) && (x0 + 1 < 64);
        w00 = (vy0 && vx0) ? w00 : 0.f; w01 = (vy0 && vx1) ? w01 : 0.f;
        w10 = (vy1 && vx0) ? w10 : 0.f; w11 = (vy1 && vx1) ? w11 : 0.f;
        int y0c = min(max(y0, 0), 63), y1c = min(max(y0 + 1, 0), 63);
        int x0c = min(max(x0, 0), 63), x1c = min(max(x0 + 1, 0), 63);
        float c00[8], c01[8], c10[8], c11[8];
        LOAD8(c00, kvb + ((size_t)((y0c << 6) + x0c) << 9) + 256 + lane * 8);
        LOAD8(c01, kvb + ((size_t)((y0c << 6) + x1c) << 9) + 256 + lane * 8);
        LOAD8(c10, kvb + ((size_t)((y1c << 6) + x0c) << 9) + 256 + lane * 8);
        LOAD8(c11, kvb + ((size_t)((y1c << 6) + x1c) << 9) + 256 + lane * 8);
#pragma unroll
        for (int h = 0; h < 8; h++) {
            float vv = w00 * c00[h] + w01 * c01[h] + w10 * c10[h] + w11 * c11[h];
            acc[h] += sh[warp][o][h] * vv;
        }
    }
    float4* po = reinterpret_cast<float4*>(outp + (size_t)p * 256 + lane * 8);
    po[0] = make_float4(acc[0], acc[1], acc[2], acc[3]);
    po[1] = make_float4(acc[4], acc[5], acc[6], acc[7]);
}

// ---------------- host ----------------
extern "C" void kernel_launch(void* const* d_in, const int* in_sizes, int n_in,
                              void* d_out, int out_size) {
    const float* x_q    = (const float*)d_in[0];
    const float* x_kv   = (const float*)d_in[1];
    const float* n1w    = (const float*)d_in[2];
    const float* n1b    = (const float*)d_in[3];
    const float* q_w    = (const float*)d_in[4];
    const float* q_b    = (const float*)d_in[5];
    const float* kv_w   = (const float*)d_in[6];
    const float* kv_b   = (const float*)d_in[7];
    const float* off1_w = (const float*)d_in[8];
    const float* off1_b = (const float*)d_in[9];
    const float* off2_w = (const float*)d_in[10];
    const float* off2_b = (const float*)d_in[11];
    const float* proj_w = (const float*)d_in[12];
    const float* proj_b = (const float*)d_in[13];
    const float* n2w    = (const float*)d_in[14];
    const float* n2b    = (const float*)d_in[15];
    const float* fc1_w  = (const float*)d_in[16];
    const float* fc1_b  = (const float*)d_in[17];
    const float* fc2_w  = (const float*)d_in[18];
    const float* fc2_b  = (const float*)d_in[19];
    float* out = (float*)d_out;

    float *xall, *qb, *kvb, *h1, *offs, *att, *xres, *xn2, *hid, *wr, *st1, *st2;
    cudaGetSymbolAddress((void**)&xall, g_xall);
    cudaGetSymbolAddress((void**)&qb,   g_q);
    cudaGetSymbolAddress((void**)&kvb,  g_kv);
    cudaGetSymbolAddress((void**)&h1,   g_h1);
    cudaGetSymbolAddress((void**)&offs, g_offs);
    cudaGetSymbolAddress((void**)&att,  g_att);
    cudaGetSymbolAddress((void**)&xres, g_xres);
    cudaGetSymbolAddress((void**)&xn2,  g_xn2);
    cudaGetSymbolAddress((void**)&hid,  g_hid);
    cudaGetSymbolAddress((void**)&wr,   g_wr);
    cudaGetSymbolAddress((void**)&st1,  g_st1);
    cudaGetSymbolAddress((void**)&st2,  g_st2);

    const int SMEM = 3 * STG_BYTES;   // 98304
    cudaFuncSetAttribute(gemm_tc<1, false>, cudaFuncAttributeMaxDynamicSharedMemorySize, SMEM);
    cudaFuncSetAttribute(gemm_tc<0, false>, cudaFuncAttributeMaxDynamicSharedMemorySize, SMEM);
    cudaFuncSetAttribute(gemm_tc<2, true >, cudaFuncAttributeMaxDynamicSharedMemorySize, SMEM);
    cudaFuncSetAttribute(gemm_tc<4, false>, cudaFuncAttributeMaxDynamicSharedMemorySize, SMEM);
    cudaFuncSetAttribute(gemm_tc<3, false>, cudaFuncAttributeMaxDynamicSharedMemorySize, SMEM);
    cudaFuncSetAttribute(gemm_tc<5, false>, cudaFuncAttributeMaxDynamicSharedMemorySize, SMEM);

    repack_k<<<4608, 256>>>(off1_w, wr);
    gn_stats_k<<<8, 512>>>(x_q, x_kv, st1);
    norm_pack_k<<<dim3(128, 8, 8), dim3(32, 8)>>>(x_q, x_kv, st1, n1w, n1b, xall);

    gemm_tc<1, false><<<dim3(2, 128), 256, SMEM>>>(xall, q_w, q_b, qb, 256, 256, 512,
                                                   nullptr, 0.17677669529663689f);
    gemm_tc<0, false><<<dim3(4, 128), 256, SMEM>>>(xall + 256, kv_w, kv_b, kvb, 512, 256, 512,
                                                   nullptr, 0.f);
    gemm_tc<2, true ><<<dim3(2, 128), 256, SMEM>>>(xall, wr, off1_b, h1, 256, 4608, 512,
                                                   nullptr, 0.f);
    off2_k<<<(MTOT * 18) / 256, 256>>>(h1, off2_w, off2_b, offs);
    attn_k<<<2048, 256>>>(qb, kvb, offs, att);
    gemm_tc<4, false><<<dim3(2, 128), 256, SMEM>>>(att, proj_w, proj_b, xres, 256, 256, 256,
                                                   x_q, 0.f);
    gn_stats_k<<<4, 512>>>(xres, xres, st2);
    norm2_k<<<(MTOT * 256) / 256, 256>>>(xres, st2, n2w, n2b, xn2);
    gemm_tc<3, false><<<dim3(8, 128), 256, SMEM>>>(xn2, fc1_w, fc1_b, hid, 1024, 256, 256,
                                                   nullptr, 0.f);
    gemm_tc<5, false><<<dim3(2, 128), 256, SMEM>>>(hid, fc2_w, fc2_b, out, 256, 1024, 1024,
                                                   xres, 0.f);
}

// round 6
// speedup vs baseline: 2.9530x; 1.0255x over previous
#include <cuda_runtime.h>
#include <math.h>
#include <stdint.h>

#define MTOT 16384

// ---------------- scratch ----------------
__device__ float g_xall[(size_t)MTOT * 512];
__device__ float g_q   [(size_t)MTOT * 256];
__device__ float g_kv  [(size_t)MTOT * 512];
__device__ float g_h1  [(size_t)MTOT * 256];
__device__ float g_offs[(size_t)MTOT * 18];
__device__ float g_att [(size_t)MTOT * 256];
__device__ float g_xres[(size_t)MTOT * 256];
__device__ float g_xn2 [(size_t)MTOT * 256];
__device__ float g_hid [(size_t)MTOT * 1024];
__device__ float g_wr  [256 * 4608];
__device__ float2 g_part[256];
__device__ float g_st1 [16];
__device__ float g_st2 [8];

// ---------------- conv weight repack ----------------
__global__ void repack_k(const float* __restrict__ w, float* __restrict__ wr) {
    int id = blockIdx.x * blockDim.x + threadIdx.x;
    if (id >= 256 * 4608) return;
    int o = id / 4608, k = id - o * 4608;
    int nb = k >> 9, c = k & 511;
    int ky = nb / 3, kx = nb - ky * 3;
    wr[id] = w[((size_t)o * 512 + c) * 9 + ky * 3 + kx];
}

// ---------------- groupnorm stats: phase 1 (32 chunks per slab) ----------------
__global__ void gn_p1(const float* __restrict__ A, const float* __restrict__ B2,
                      float2* __restrict__ part) {
    int bi = blockIdx.x;
    int slab = bi >> 5, chunk = bi & 31;
    int tensor = slab >> 2, batch = slab & 3;
    const float* src = (tensor ? B2 : A) + ((size_t)batch << 20) + ((size_t)chunk << 15);
    const float4* p4 = reinterpret_cast<const float4*>(src);
    float s = 0.f, s2 = 0.f;
    for (int i = threadIdx.x; i < 8192; i += 256) {
        float4 v = p4[i];
        s  += v.x + v.y + v.z + v.w;
        s2 += v.x * v.x + v.y * v.y + v.z * v.z + v.w * v.w;
    }
    __shared__ float sh1[256], sh2[256];
    sh1[threadIdx.x] = s; sh2[threadIdx.x] = s2;
    __syncthreads();
    for (int st = 128; st > 0; st >>= 1) {
        if (threadIdx.x < st) { sh1[threadIdx.x] += sh1[threadIdx.x + st];
                                sh2[threadIdx.x] += sh2[threadIdx.x + st]; }
        __syncthreads();
    }
    if (threadIdx.x == 0) part[slab * 32 + chunk] = make_float2(sh1[0], sh2[0]);
}

// ---------------- groupnorm stats: phase 2 ----------------
__global__ void gn_p2(const float2* __restrict__ part, float* __restrict__ stats, int nslab) {
    int slab = threadIdx.x >> 5, lane = threadIdx.x & 31;
    if (slab >= nslab) return;
    float2 v = part[slab * 32 + lane];
    float s = v.x, s2 = v.y;
#pragma unroll
    for (int off = 16; off > 0; off >>= 1) {
        s  += __shfl_xor_sync(0xffffffffu, s,  off);
        s2 += __shfl_xor_sync(0xffffffffu, s2, off);
    }
    if (lane == 0) {
        float inv = 1.f / 1048576.f;
        float mu = s * inv;
        float var = s2 * inv - mu * mu;
        stats[slab * 2] = mu;
        stats[slab * 2 + 1] = rsqrtf(var + 1e-5f);
    }
}

// ---------------- normalize + NCHW->NHWC pack ----------------
__global__ void norm_pack_k(const float* __restrict__ xq, const float* __restrict__ xkv,
                            const float* __restrict__ stats, const float* __restrict__ w,
                            const float* __restrict__ bb, float* __restrict__ xall) {
    __shared__ float tile[32][33];
    int bz = blockIdx.z;
    int tensor = bz >> 2, batch = bz & 3;
    const float* src = (tensor == 0 ? xq : xkv) + ((size_t)batch << 20);
    float mu = stats[bz * 2], rstd = stats[bz * 2 + 1];
    int s0 = blockIdx.x * 32, c0 = blockIdx.y * 32;
    int tx = threadIdx.x, ty = threadIdx.y;
#pragma unroll
    for (int k = 0; k < 4; k++) {
        int c = c0 + ty + k * 8;
        tile[ty + k * 8][tx] = src[(size_t)c * 4096 + s0 + tx];
    }
    __syncthreads();
#pragma unroll
    for (int k = 0; k < 4; k++) {
        int sl = ty + k * 8;
        int c = c0 + tx;
        float v = (tile[tx][sl] - mu) * rstd * w[c] + bb[c];
        xall[(((size_t)batch * 4096 + s0 + sl) << 9) + tensor * 256 + c] = v;
    }
}

// ---------------- norm2 ----------------
__global__ void norm2_k(const float* __restrict__ xres, const float* __restrict__ stats,
                        const float* __restrict__ w, const float* __restrict__ bb,
                        float* __restrict__ xn) {
    int id = blockIdx.x * blockDim.x + threadIdx.x;
    if (id >= MTOT * 256) return;
    int b = id >> 20, c = id & 255;
    xn[id] = (xres[id] - stats[b * 2]) * stats[b * 2 + 1] * w[c] + bb[c];
}

// ---------------- PTX helpers ----------------
__device__ __forceinline__ void mma8(float4& d, const uint32_t* a, const uint32_t* b) {
    asm volatile("mma.sync.aligned.m16n8k8.row.col.f32.tf32.tf32.f32 "
        "{%0,%1,%2,%3}, {%4,%5,%6,%7}, {%8,%9}, {%0,%1,%2,%3};\n"
        : "+f"(d.x), "+f"(d.y), "+f"(d.z), "+f"(d.w)
        : "r"(a[0]), "r"(a[1]), "r"(a[2]), "r"(a[3]), "r"(b[0]), "r"(b[1]));
}
__device__ __forceinline__ void ldsm4(uint32_t* r, uint32_t a) {
    asm volatile("ldmatrix.sync.aligned.m8n8.x4.shared.b16 {%0,%1,%2,%3}, [%4];"
        : "=r"(r[0]), "=r"(r[1]), "=r"(r[2]), "=r"(r[3]) : "r"(a));
}
__device__ __forceinline__ void cp16(uint32_t d, const void* s, int sz) {
    asm volatile("cp.async.cg.shared.global [%0], [%1], 16, %2;"
        :: "r"(d), "l"(s), "r"(sz));
}
#define CP_COMMIT() asm volatile("cp.async.commit_group;")

// ---------------- multi-job tf32 tensor-core GEMM ----------------
// Per job: C[M,N] = A[M,K] @ W[N,K]^T + bias, M = 16384 always.
// mode 0 plain / 1 *scale / 2 relu / 3 gelu / 4 +R(NCHW)->NHWC / 5 +R(NHWC)->NCHW
// CTA tile 128x128x32, 256 thr, 3-stage cp.async, ldmatrix (A: 4x ldsm4, B: 2x ldsm4).
#define STG_BYTES 32768
#define SMEM_REQ  (3 * STG_BYTES)

struct GJob {
    const float* A; const float* W; const float* bias; float* C; const float* R;
    int N, K, lda, mode, im2col; float scale;
};

__device__ __forceinline__ void issue_tile(
    uint32_t sa0, const float* __restrict__ A, const float* __restrict__ W,
    int bm, int bn, int K0, int lda, int K, int im2col, int lrow, int g)
{
    uint32_t sa = sa0 + lrow * 128;
    const float* srcA; int szA = 16;
    if (!im2col) {
        srcA = A + (size_t)(bm + lrow) * lda + K0;
    } else {
        const int gm = bm + lrow;
        const int ib = gm >> 12, sp = gm & 4095;
        const int iy = sp >> 6, ix = sp & 63;
        const int nb = K0 >> 9, cc0 = K0 & 511;
        const int qy = nb / 3;
        const int yy = iy + qy - 1, xx = ix + (nb - qy * 3) - 1;
        srcA = A + (((size_t)(ib << 12) + (yy << 6) + xx) << 9) + cc0;
        if (!(yy >= 0 && yy < 64 && xx >= 0 && xx < 64)) { szA = 0; srcA = A; }
    }
    const float* srcB = W + (size_t)(bn + lrow) * (size_t)K + K0;
    const int r7 = lrow & 7;
#pragma unroll
    for (int j = 0; j < 4; j++) {
        const int c = g + j;
        const uint32_t off = (uint32_t)((c ^ r7) << 4);
        cp16(sa + off, srcA + c * 4, szA);
        cp16(sa + 16384 + off, srcB + c * 4, 16);
    }
}

__global__ void __launch_bounds__(256, 2) gemm_tc(
    GJob j0, GJob j1, GJob j2, int c0, int c1)
{
    extern __shared__ float smbuf[];
    const uint32_t smem_base = (uint32_t)__cvta_generic_to_shared(smbuf);

    // ---- job decode ----
    GJob J;
    int local;
    {
        const int id = blockIdx.x;
        if (id < c0)      { J = j0; local = id; }
        else if (id < c1) { J = j1; local = id - c0; }
        else              { J = j2; local = id - c1; }
    }
    const int bnb = J.N >> 7;
    const int bm = (local / bnb) << 7, bn = (local % bnb) << 7;

    const int tid  = threadIdx.x;
    const int warp = tid >> 5, lane = tid & 31;
    const int wm   = (warp >> 2) << 6, wn = (warp & 3) << 5;
    const int lg   = lane >> 2, la3 = lane & 3;

    const int lrow = tid >> 1, g = (tid & 1) * 4;

    // ldmatrix per-lane constants
    const int l7 = lane & 7, lq = lane >> 3;
    uint32_t arow[4], brow[2];
#pragma unroll
    for (int mt = 0; mt < 4; mt++)
        arow[mt] = (uint32_t)((wm + mt * 16 + ((lq & 1) << 3) + l7) * 128);
    const int a_kq = lq >> 1;
    // B x4: matrices {n+0/khalf0, n+0/khalf1, n+8/khalf0, n+8/khalf1}
#pragma unroll
    for (int p = 0; p < 2; p++)
        brow[p] = (uint32_t)(16384 + (wn + p * 16 + ((lq >> 1) << 3) + l7) * 128);
    const int b_kq = lq & 1;

    float4 acc[4][4];
#pragma unroll
    for (int i = 0; i < 4; i++)
#pragma unroll
        for (int j = 0; j < 4; j++) acc[i][j] = make_float4(0.f, 0.f, 0.f, 0.f);

    const int nkb = J.K >> 5;
    issue_tile(smem_base,             J.A, J.W, bm, bn,  0, J.lda, J.K, J.im2col, lrow, g);
    CP_COMMIT();
    issue_tile(smem_base + STG_BYTES, J.A, J.W, bm, bn, 32, J.lda, J.K, J.im2col, lrow, g);
    CP_COMMIT();

    int stg = 0;
    for (int kb = 0; kb < nkb; kb++) {
        asm volatile("cp.async.wait_group 1;");
        __syncthreads();
        if (kb + 2 < nkb) {
            int s2 = stg + 2; if (s2 >= 3) s2 -= 3;
            issue_tile(smem_base + s2 * STG_BYTES, J.A, J.W, bm, bn,
                       (kb + 2) << 5, J.lda, J.K, J.im2col, lrow, g);
        }
        CP_COMMIT();

        const uint32_t Ab = smem_base + stg * STG_BYTES;
#pragma unroll
        for (int ks = 0; ks < 4; ks++) {
            const uint32_t axor = (uint32_t)((((ks << 1) + a_kq) ^ l7) << 4);
            const uint32_t bxor = (uint32_t)((((ks << 1) + b_kq) ^ l7) << 4);
            uint32_t af[4][4], bf[2][4];
#pragma unroll
            for (int mt = 0; mt < 4; mt++) ldsm4(af[mt], Ab + arow[mt] + axor);
#pragma unroll
            for (int p = 0; p < 2; p++)    ldsm4(bf[p],  Ab + brow[p] + bxor);
#pragma unroll
            for (int mt = 0; mt < 4; mt++) {
                mma8(acc[mt][0], af[mt], &bf[0][0]);
                mma8(acc[mt][1], af[mt], &bf[0][2]);
                mma8(acc[mt][2], af[mt], &bf[1][0]);
                mma8(acc[mt][3], af[mt], &bf[1][2]);
            }
        }
        if (++stg == 3) stg = 0;
    }

    // ---------------- epilogue ----------------
#pragma unroll
    for (int mt = 0; mt < 4; mt++) {
        const int m0 = bm + wm + (mt << 4) + lg;
#pragma unroll
        for (int nt = 0; nt < 4; nt++) {
            const int n = bn + wn + (nt << 3) + (la3 << 1);
            const float b0 = J.bias[n], b1 = J.bias[n + 1];
            float v[4] = {acc[mt][nt].x + b0, acc[mt][nt].y + b1,
                          acc[mt][nt].z + b0, acc[mt][nt].w + b1};
#pragma unroll
            for (int h = 0; h < 2; h++) {
                const int m = m0 + h * 8;
#pragma unroll
                for (int j = 0; j < 2; j++) {
                    float x = v[h * 2 + j];
                    const int nn = n + j;
                    if (J.mode == 1) x *= J.scale;
                    else if (J.mode == 2) x = fmaxf(x, 0.f);
                    else if (J.mode == 3) x = 0.5f * x * (1.f + erff(x * 0.70710678118654752f));
                    else if (J.mode == 4) x += J.R[((size_t)(m >> 12) * 256 + nn) * 4096 + (m & 4095)];
                    else if (J.mode == 5) x += J.R[(size_t)m * 256 + nn];
                    if (J.mode == 5)
                        J.C[((size_t)(m >> 12) * 256 + nn) * 4096 + (m & 4095)] = x;
                    else
                        J.C[(size_t)m * (size_t)J.N + nn] = x;
                }
            }
        }
    }
}

// ---------------- offset head ----------------
__global__ void off2_k(const float* __restrict__ h1, const float* __restrict__ w,
                       const float* __restrict__ bias, float* __restrict__ offs) {
    int id = blockIdx.x * blockDim.x + threadIdx.x;
    if (id >= MTOT * 18) return;
    int m = id / 18, n = id - m * 18;
    const float4* a = reinterpret_cast<const float4*>(h1 + (size_t)m * 256);
    const float4* ww = reinterpret_cast<const float4*>(w + (size_t)n * 256);
    float s = bias[n];
#pragma unroll 8
    for (int k = 0; k < 64; k++) {
        float4 av = a[k], wv = ww[k];
        s += av.x * wv.x + av.y * wv.y + av.z * wv.z + av.w * wv.w;
    }
    offs[id] = s;
}

// ---------------- fused bilinear-sample + 9-way attention ----------------
#define LOAD8(dst, ptr)                                                     \
    {                                                                       \
        float4 _u0 = *reinterpret_cast<const float4*>(ptr);                 \
        float4 _u1 = *reinterpret_cast<const float4*>((ptr) + 4);           \
        dst[0] = _u0.x; dst[1] = _u0.y; dst[2] = _u0.z; dst[3] = _u0.w;     \
        dst[4] = _u1.x; dst[5] = _u1.y; dst[6] = _u1.z; dst[7] = _u1.w;     \
    }

__global__ void __launch_bounds__(256) attn_k(
    const float* __restrict__ qb, const float* __restrict__ kv,
    const float* __restrict__ offs, float* __restrict__ outp) {
    __shared__ float sh[8][9][8];
    const int warp = threadIdx.x >> 5, lane = threadIdx.x & 31;
    const int p = blockIdx.x * 8 + warp;
    const int b = p >> 12, s = p & 4095, y = s >> 6, x = s & 63;
    const float* kvb = kv + (((size_t)b << 12) << 9);

    float qr[8];
    LOAD8(qr, qb + (size_t)p * 256 + lane * 8);

    for (int o = 0; o < 9; o++) {
        int ys = y + o / 3 - 1, xs = x + o % 3 - 1;
        float prod[8] = {0.f, 0.f, 0.f, 0.f, 0.f, 0.f, 0.f, 0.f};
        if (ys >= 0 && ys < 64 && xs >= 0 && xs < 64) {
            const float* op = offs + (size_t)((b << 12) + (ys << 6) + xs) * 18 + 2 * o;
            float px = op[0], py = op[1];
            float y0f = floorf(py), x0f = floorf(px);
            float wy = py - y0f, wx = px - x0f;
            int y0 = (int)y0f, x0 = (int)x0f;
            float w00 = (1.f - wy) * (1.f - wx), w01 = (1.f - wy) * wx;
            float w10 = wy * (1.f - wx), w11 = wy * wx;
            bool vy0 = (y0 >= 0) && (y0 < 64), vy1 = (y0 + 1 >= 0) && (y0 + 1 < 64);
            bool vx0 = (x0 >= 0) && (x0 < 64), vx1 = (x0 + 1 >= 0) && (x0 + 1 < 64);
            w00 = (vy0 && vx0) ? w00 : 0.f; w01 = (vy0 && vx1) ? w01 : 0.f;
            w10 = (vy1 && vx0) ? w10 : 0.f; w11 = (vy1 && vx1) ? w11 : 0.f;
            int y0c = min(max(y0, 0), 63), y1c = min(max(y0 + 1, 0), 63);
            int x0c = min(max(x0, 0), 63), x1c = min(max(x0 + 1, 0), 63);
            float c00[8], c01[8], c10[8], c11[8];
            LOAD8(c00, kvb + ((size_t)((y0c << 6) + x0c) << 9) + lane * 8);
            LOAD8(c01, kvb + ((size_t)((y0c << 6) + x1c) << 9) + lane * 8);
            LOAD8(c10, kvb + ((size_t)((y1c << 6) + x0c) << 9) + lane * 8);
            LOAD8(c11, kvb + ((size_t)((y1c << 6) + x1c) << 9) + lane * 8);
#pragma unroll
            for (int h = 0; h < 8; h++) {
                float kvv = w00 * c00[h] + w01 * c01[h] + w10 * c10[h] + w11 * c11[h];
                prod[h] = qr[h] * kvv;
            }
        }
#pragma unroll
        for (int off = 16; off > 0; off >>= 1)
#pragma unroll
            for (int h = 0; h < 8; h++)
                prod[h] += __shfl_xor_sync(0xffffffffu, prod[h], off);
        if (lane == 0) {
#pragma unroll
            for (int h = 0; h < 8; h++) sh[warp][o][h] = prod[h];
        }
    }
    __syncwarp();
    if (lane < 8) {
        float e[9]; float mx = -1e30f;
#pragma unroll
        for (int o = 0; o < 9; o++) { e[o] = sh[warp][o][lane]; mx = fmaxf(mx, e[o]); }
        float sm = 0.f;
#pragma unroll
        for (int o = 0; o < 9; o++) { e[o] = expf(e[o] - mx); sm += e[o]; }
        float inv = 1.f / sm;
#pragma unroll
        for (int o = 0; o < 9; o++) sh[warp][o][lane] = e[o] * inv;
    }
    __syncwarp();
    float acc[8] = {0.f, 0.f, 0.f, 0.f, 0.f, 0.f, 0.f, 0.f};
    for (int o = 0; o < 9; o++) {
        int ys = y + o / 3 - 1, xs = x + o % 3 - 1;
        if (ys < 0 || ys >= 64 || xs < 0 || xs >= 64) continue;
        const float* op = offs + (size_t)((b << 12) + (ys << 6) + xs) * 18 + 2 * o;
        float px = op[0], py = op[1];
        float y0f = floorf(py), x0f = floorf(px);
        float wy = py - y0f, wx = px - x0f;
        int y0 = (int)y0f, x0 = (int)x0f;
        float w00 = (1.f - wy) * (1.f - wx), w01 = (1.f - wy) * wx;
        float w10 = wy * (1.f - wx), w11 = wy * wx;
        bool vy0 = (y0 >= 0) && (y0 < 64), vy1 = (y0 + 1 >= 0) && (y0 + 1 < 64);
        bool vx0 = (x0 >= 0) && (x0 < 64), vx1 = (x0 + 1 >= 0) && (x0 + 1 < 64);
        w00 = (vy0 && vx0) ? w00 : 0.f; w01 = (vy0 && vx1) ? w01 : 0.f;
        w10 = (vy1 && vx0) ? w10 : 0.f; w11 = (vy1 && vx1) ? w11 : 0.f;
        int y0c = min(max(y0, 0), 63), y1c = min(max(y0 + 1, 0), 63);
        int x0c = min(max(x0, 0), 63), x1c = min(max(x0 + 1, 0), 63);
        float c00[8], c01[8], c10[8], c11[8];
        LOAD8(c00, kvb + ((size_t)((y0c << 6) + x0c) << 9) + 256 + lane * 8);
        LOAD8(c01, kvb + ((size_t)((y0c << 6) + x1c) << 9) + 256 + lane * 8);
        LOAD8(c10, kvb + ((size_t)((y1c << 6) + x0c) << 9) + 256 + lane * 8);
        LOAD8(c11, kvb + ((size_t)((y1c << 6) + x1c) << 9) + 256 + lane * 8);
#pragma unroll
        for (int h = 0; h < 8; h++) {
            float vv = w00 * c00[h] + w01 * c01[h] + w10 * c10[h] + w11 * c11[h];
            acc[h] += sh[warp][o][h] * vv;
        }
    }
    float4* po = reinterpret_cast<float4*>(outp + (size_t)p * 256 + lane * 8);
    po[0] = make_float4(acc[0], acc[1], acc[2], acc[3]);
    po[1] = make_float4(acc[4], acc[5], acc[6], acc[7]);
}

// ---------------- host ----------------
extern "C" void kernel_launch(void* const* d_in, const int* in_sizes, int n_in,
                              void* d_out, int out_size) {
    const float* x_q    = (const float*)d_in[0];
    const float* x_kv   = (const float*)d_in[1];
    const float* n1w    = (const float*)d_in[2];
    const float* n1b    = (const float*)d_in[3];
    const float* q_w    = (const float*)d_in[4];
    const float* q_b    = (const float*)d_in[5];
    const float* kv_w   = (const float*)d_in[6];
    const float* kv_b   = (const float*)d_in[7];
    const float* off1_w = (const float*)d_in[8];
    const float* off1_b = (const float*)d_in[9];
    const float* off2_w = (const float*)d_in[10];
    const float* off2_b = (const float*)d_in[11];
    const float* proj_w = (const float*)d_in[12];
    const float* proj_b = (const float*)d_in[13];
    const float* n2w    = (const float*)d_in[14];
    const float* n2b    = (const float*)d_in[15];
    const float* fc1_w  = (const float*)d_in[16];
    const float* fc1_b  = (const float*)d_in[17];
    const float* fc2_w  = (const float*)d_in[18];
    const float* fc2_b  = (const float*)d_in[19];
    float* out = (float*)d_out;

    float *xall, *qb, *kvb, *h1, *offs, *att, *xres, *xn2, *hid, *wr, *st1, *st2;
    float2* part;
    cudaGetSymbolAddress((void**)&xall, g_xall);
    cudaGetSymbolAddress((void**)&qb,   g_q);
    cudaGetSymbolAddress((void**)&kvb,  g_kv);
    cudaGetSymbolAddress((void**)&h1,   g_h1);
    cudaGetSymbolAddress((void**)&offs, g_offs);
    cudaGetSymbolAddress((void**)&att,  g_att);
    cudaGetSymbolAddress((void**)&xres, g_xres);
    cudaGetSymbolAddress((void**)&xn2,  g_xn2);
    cudaGetSymbolAddress((void**)&hid,  g_hid);
    cudaGetSymbolAddress((void**)&wr,   g_wr);
    cudaGetSymbolAddress((void**)&part, g_part);
    cudaGetSymbolAddress((void**)&st1,  g_st1);
    cudaGetSymbolAddress((void**)&st2,  g_st2);

    cudaFuncSetAttribute(gemm_tc, cudaFuncAttributeMaxDynamicSharedMemorySize, SMEM_REQ);

    repack_k<<<4608, 256>>>(off1_w, wr);
    gn_p1<<<256, 256>>>(x_q, x_kv, part);
    gn_p2<<<1, 256>>>(part, st1, 8);
    norm_pack_k<<<dim3(128, 8, 8), dim3(32, 8)>>>(x_q, x_kv, st1, n1w, n1b, xall);

    GJob zero = {};
    // fused q + kv + conv (conv first: longest blocks launch earliest)
    {
        GJob jc  = {xall,       wr,   off1_b, h1,  nullptr, 256, 4608, 512, 2, 1, 0.f};
        GJob jkv = {xall + 256, kv_w, kv_b,   kvb, nullptr, 512, 256,  512, 0, 0, 0.f};
        GJob jq  = {xall,       q_w,  q_b,    qb,  nullptr, 256, 256,  512, 1, 0,
                    0.17677669529663689f};
        gemm_tc<<<1024, 256, SMEM_REQ>>>(jc, jkv, jq, 256, 768);
    }
    off2_k<<<(MTOT * 18) / 256, 256>>>(h1, off2_w, off2_b, offs);
    attn_k<<<2048, 256>>>(qb, kvb, offs, att);
    // xres = x_q + att @ proj_w^T + b
    {
        GJob jp = {att, proj_w, proj_b, xres, x_q, 256, 256, 256, 4, 0, 0.f};
        gemm_tc<<<256, 256, SMEM_REQ>>>(jp, zero, zero, 256, 256);
    }
    gn_p1<<<128, 256>>>(xres, xres, part);
    gn_p2<<<1, 256>>>(part, st2, 4);
    norm2_k<<<(MTOT * 256) / 256, 256>>>(xres, st2, n2w, n2b, xn2);
    // hid = gelu(xn2 @ fc1_w^T + b)
    {
        GJob jf1 = {xn2, fc1_w, fc1_b, hid, nullptr, 1024, 256, 256, 3, 0, 0.f};
        gemm_tc<<<1024, 256, SMEM_REQ>>>(jf1, zero, zero, 1024, 1024);
    }
    // out(NCHW) = xres + hid @ fc2_w^T + b
    {
        GJob jf2 = {hid, fc2_w, fc2_b, out, xres, 256, 1024, 1024, 5, 0, 0.f};
        gemm_tc<<<256, 256, SMEM_REQ>>>(jf2, zero, zero, 256, 256);
    }
}

// round 7
// speedup vs baseline: 4.1534x; 1.4065x over previous
#include <cuda_runtime.h>
#include <cuda_fp16.h>
#include <math.h>
#include <stdint.h>

#define MTOT 16384

// ---------------- scratch ----------------
__device__ __align__(1024) __half g_xall[(size_t)MTOT * 512];
__device__ float  g_q   [(size_t)MTOT * 256];
__device__ float  g_kv  [(size_t)MTOT * 512];
__device__ float  g_h1  [(size_t)MTOT * 256];
__device__ float  g_offs[(size_t)MTOT * 18];
__device__ __align__(1024) __half g_att [(size_t)MTOT * 256];
__device__ float  g_xres[(size_t)MTOT * 256];
__device__ __align__(1024) __half g_xn2 [(size_t)MTOT * 256];
__device__ __align__(1024) __half g_hid [(size_t)MTOT * 1024];
__device__ __align__(1024) __half g_wr  [256 * 4608];
__device__ __align__(1024) __half g_wh  [65536 + 131072 + 65536 + 262144 + 262144];
__device__ float2 g_part[256];
__device__ float  g_st1 [16];
__device__ float  g_st2 [8];

// ---------------- fp32 -> fp16 convert ----------------
__global__ void f2h_k(const float* __restrict__ s, __half* __restrict__ d, int n) {
    int i = blockIdx.x * 256 + threadIdx.x;
    if (i < n) d[i] = __float2half(s[i]);
}

// ---------------- conv weight repack (fp16 out) ----------------
__global__ void repack_k(const float* __restrict__ w, __half* __restrict__ wr) {
    int id = blockIdx.x * blockDim.x + threadIdx.x;
    if (id >= 256 * 4608) return;
    int o = id / 4608, k = id - o * 4608;
    int nb = k >> 9, c = k & 511;
    int ky = nb / 3, kx = nb - ky * 3;
    wr[id] = __float2half(w[((size_t)o * 512 + c) * 9 + ky * 3 + kx]);
}

// ---------------- groupnorm stats: phase 1 ----------------
__global__ void gn_p1(const float* __restrict__ A, const float* __restrict__ B2,
                      float2* __restrict__ part) {
    int bi = blockIdx.x;
    int slab = bi >> 5, chunk = bi & 31;
    int tensor = slab >> 2, batch = slab & 3;
    const float* src = (tensor ? B2 : A) + ((size_t)batch << 20) + ((size_t)chunk << 15);
    const float4* p4 = reinterpret_cast<const float4*>(src);
    float s = 0.f, s2 = 0.f;
    for (int i = threadIdx.x; i < 8192; i += 256) {
        float4 v = p4[i];
        s  += v.x + v.y + v.z + v.w;
        s2 += v.x * v.x + v.y * v.y + v.z * v.z + v.w * v.w;
    }
    __shared__ float sh1[256], sh2[256];
    sh1[threadIdx.x] = s; sh2[threadIdx.x] = s2;
    __syncthreads();
    for (int st = 128; st > 0; st >>= 1) {
        if (threadIdx.x < st) { sh1[threadIdx.x] += sh1[threadIdx.x + st];
                                sh2[threadIdx.x] += sh2[threadIdx.x + st]; }
        __syncthreads();
    }
    if (threadIdx.x == 0) part[slab * 32 + chunk] = make_float2(sh1[0], sh2[0]);
}

// ---------------- groupnorm stats: phase 2 ----------------
__global__ void gn_p2(const float2* __restrict__ part, float* __restrict__ stats, int nslab) {
    int slab = threadIdx.x >> 5, lane = threadIdx.x & 31;
    if (slab >= nslab) return;
    float2 v = part[slab * 32 + lane];
    float s = v.x, s2 = v.y;
#pragma unroll
    for (int off = 16; off > 0; off >>= 1) {
        s  += __shfl_xor_sync(0xffffffffu, s,  off);
        s2 += __shfl_xor_sync(0xffffffffu, s2, off);
    }
    if (lane == 0) {
        float inv = 1.f / 1048576.f;
        float mu = s * inv;
        float var = s2 * inv - mu * mu;
        stats[slab * 2] = mu;
        stats[slab * 2 + 1] = rsqrtf(var + 1e-5f);
    }
}

// ---------------- normalize + NCHW->NHWC pack (fp16 out) ----------------
__global__ void norm_pack_k(const float* __restrict__ xq, const float* __restrict__ xkv,
                            const float* __restrict__ stats, const float* __restrict__ w,
                            const float* __restrict__ bb, __half* __restrict__ xall) {
    __shared__ float tile[32][33];
    int bz = blockIdx.z;
    int tensor = bz >> 2, batch = bz & 3;
    const float* src = (tensor == 0 ? xq : xkv) + ((size_t)batch << 20);
    float mu = stats[bz * 2], rstd = stats[bz * 2 + 1];
    int s0 = blockIdx.x * 32, c0 = blockIdx.y * 32;
    int tx = threadIdx.x, ty = threadIdx.y;
#pragma unroll
    for (int k = 0; k < 4; k++) {
        int c = c0 + ty + k * 8;
        tile[ty + k * 8][tx] = src[(size_t)c * 4096 + s0 + tx];
    }
    __syncthreads();
#pragma unroll
    for (int k = 0; k < 4; k++) {
        int sl = ty + k * 8;
        int c = c0 + tx;
        float v = (tile[tx][sl] - mu) * rstd * w[c] + bb[c];
        xall[(((size_t)batch * 4096 + s0 + sl) << 9) + tensor * 256 + c] = __float2half(v);
    }
}

// ---------------- norm2 (fp16 out) ----------------
__global__ void norm2_k(const float* __restrict__ xres, const float* __restrict__ stats,
                        const float* __restrict__ w, const float* __restrict__ bb,
                        __half* __restrict__ xn) {
    int id = blockIdx.x * blockDim.x + threadIdx.x;
    if (id >= MTOT * 256) return;
    int b = id >> 20, c = id & 255;
    xn[id] = __float2half((xres[id] - stats[b * 2]) * stats[b * 2 + 1] * w[c] + bb[c]);
}

// ---------------- PTX helpers ----------------
__device__ __forceinline__ void mma16(float4& d, const uint32_t* a, const uint32_t* b) {
    asm volatile("mma.sync.aligned.m16n8k16.row.col.f32.f16.f16.f32 "
        "{%0,%1,%2,%3}, {%4,%5,%6,%7}, {%8,%9}, {%0,%1,%2,%3};\n"
        : "+f"(d.x), "+f"(d.y), "+f"(d.z), "+f"(d.w)
        : "r"(a[0]), "r"(a[1]), "r"(a[2]), "r"(a[3]), "r"(b[0]), "r"(b[1]));
}
__device__ __forceinline__ void ldsm4(uint32_t* r, uint32_t a) {
    asm volatile("ldmatrix.sync.aligned.m8n8.x4.shared.b16 {%0,%1,%2,%3}, [%4];"
        : "=r"(r[0]), "=r"(r[1]), "=r"(r[2]), "=r"(r[3]) : "r"(a));
}
__device__ __forceinline__ void cp16(uint32_t d, const void* s, int sz) {
    asm volatile("cp.async.cg.shared.global [%0], [%1], 16, %2;"
        :: "r"(d), "l"(s), "r"(sz));
}
#define CP_COMMIT() asm volatile("cp.async.commit_group;")

// ---------------- multi-job fp16 tensor-core GEMM ----------------
// C[M,N] = A[M,K] @ W[N,K]^T + bias (A, W fp16; accum/bias fp32). M = 16384.
// mode 0 plain / 1 *scale / 2 relu / 3 gelu->HALF out / 4 +R(NCHW)->NHWC / 5 +R(NHWC)->NCHW
// CTA tile 128x128x64(halves), 256 thr, 3-stage cp.async, mma m16n8k16.
// Stage: A 128x128B + B 128x128B = 32KB; row = 64 halves; 8 chunks/row, swz c^(row&7).
#define STG_BYTES 32768
#define SMEM_REQ  (3 * STG_BYTES)

struct GJob {
    const __half* A; const __half* W; const float* bias; float* C; const float* R;
    int N, K, lda, mode, im2col; float scale;
};

__device__ __forceinline__ void issue_tile(
    uint32_t sa0, const __half* __restrict__ A, const __half* __restrict__ W,
    int bm, int bn, int K0, int lda, int K, int im2col, int lrow, int g)
{
    uint32_t sa = sa0 + lrow * 128;
    const __half* srcA; int szA = 16;
    if (!im2col) {
        srcA = A + (size_t)(bm + lrow) * lda + K0;
    } else {
        const int gm = bm + lrow;
        const int ib = gm >> 12, sp = gm & 4095;
        const int iy = sp >> 6, ix = sp & 63;
        const int nb = K0 >> 9, cc0 = K0 & 511;
        const int qy = nb / 3;
        const int yy = iy + qy - 1, xx = ix + (nb - qy * 3) - 1;
        srcA = A + (((size_t)(ib << 12) + (yy << 6) + xx) << 9) + cc0;
        if (!(yy >= 0 && yy < 64 && xx >= 0 && xx < 64)) { szA = 0; srcA = A; }
    }
    const __half* srcB = W + (size_t)(bn + lrow) * (size_t)K + K0;
    const int r7 = lrow & 7;
#pragma unroll
    for (int j = 0; j < 4; j++) {
        const int c = g + j;
        const uint32_t off = (uint32_t)((c ^ r7) << 4);
        cp16(sa + off, srcA + c * 8, szA);
        cp16(sa + 16384 + off, srcB + c * 8, 16);
    }
}

__global__ void __launch_bounds__(256, 2) gemm_tc(
    GJob j0, GJob j1, GJob j2, int c0, int c1)
{
    extern __shared__ float smbuf[];
    const uint32_t smem_base = (uint32_t)__cvta_generic_to_shared(smbuf);

    // ---- job decode ----
    GJob J;
    int local;
    {
        const int id = blockIdx.x;
        if (id < c0)      { J = j0; local = id; }
        else if (id < c1) { J = j1; local = id - c0; }
        else              { J = j2; local = id - c1; }
    }
    const int bnb = J.N >> 7;
    const int bm = (local / bnb) << 7, bn = (local % bnb) << 7;

    const int tid  = threadIdx.x;
    const int warp = tid >> 5, lane = tid & 31;
    const int wm   = (warp >> 2) << 6, wn = (warp & 3) << 5;
    const int lg   = lane >> 2, la3 = lane & 3;

    const int lrow = tid >> 1, g = (tid & 1) * 4;

    // ldmatrix per-lane constants
    const int l7 = lane & 7, lq = lane >> 3;
    uint32_t arow[4], brow[2];
#pragma unroll
    for (int mt = 0; mt < 4; mt++)
        arow[mt] = (uint32_t)((wm + mt * 16 + ((lq & 1) << 3) + l7) * 128);
    const int a_kq = lq >> 1;
#pragma unroll
    for (int p = 0; p < 2; p++)
        brow[p] = (uint32_t)(16384 + (wn + p * 16 + ((lq >> 1) << 3) + l7) * 128);
    const int b_kq = lq & 1;

    float4 acc[4][4];
#pragma unroll
    for (int i = 0; i < 4; i++)
#pragma unroll
        for (int j = 0; j < 4; j++) acc[i][j] = make_float4(0.f, 0.f, 0.f, 0.f);

    const int nkb = J.K >> 6;
    issue_tile(smem_base,             J.A, J.W, bm, bn,  0, J.lda, J.K, J.im2col, lrow, g);
    CP_COMMIT();
    issue_tile(smem_base + STG_BYTES, J.A, J.W, bm, bn, 64, J.lda, J.K, J.im2col, lrow, g);
    CP_COMMIT();

    int stg = 0;
    for (int kb = 0; kb < nkb; kb++) {
        asm volatile("cp.async.wait_group 1;");
        __syncthreads();
        if (kb + 2 < nkb) {
            int s2 = stg + 2; if (s2 >= 3) s2 -= 3;
            issue_tile(smem_base + s2 * STG_BYTES, J.A, J.W, bm, bn,
                       (kb + 2) << 6, J.lda, J.K, J.im2col, lrow, g);
        }
        CP_COMMIT();

        const uint32_t Ab = smem_base + stg * STG_BYTES;
#pragma unroll
        for (int ks = 0; ks < 4; ks++) {
            const uint32_t axor = (uint32_t)((((ks << 1) + a_kq) ^ l7) << 4);
            const uint32_t bxor = (uint32_t)((((ks << 1) + b_kq) ^ l7) << 4);
            uint32_t af[4][4], bf[2][4];
#pragma unroll
            for (int mt = 0; mt < 4; mt++) ldsm4(af[mt], Ab + arow[mt] + axor);
#pragma unroll
            for (int p = 0; p < 2; p++)    ldsm4(bf[p],  Ab + brow[p] + bxor);
#pragma unroll
            for (int mt = 0; mt < 4; mt++) {
                mma16(acc[mt][0], af[mt], &bf[0][0]);
                mma16(acc[mt][1], af[mt], &bf[0][2]);
                mma16(acc[mt][2], af[mt], &bf[1][0]);
                mma16(acc[mt][3], af[mt], &bf[1][2]);
            }
        }
        if (++stg == 3) stg = 0;
    }

    // ---------------- epilogue ----------------
#pragma unroll
    for (int mt = 0; mt < 4; mt++) {
        const int m0 = bm + wm + (mt << 4) + lg;
#pragma unroll
        for (int nt = 0; nt < 4; nt++) {
            const int n = bn + wn + (nt << 3) + (la3 << 1);
            const float b0 = J.bias[n], b1 = J.bias[n + 1];
            float v[4] = {acc[mt][nt].x + b0, acc[mt][nt].y + b1,
                          acc[mt][nt].z + b0, acc[mt][nt].w + b1};
#pragma unroll
            for (int h = 0; h < 2; h++) {
                const int m = m0 + h * 8;
                if (J.mode == 3) {
                    float x0 = v[h * 2], x1 = v[h * 2 + 1];
                    x0 = 0.5f * x0 * (1.f + erff(x0 * 0.70710678118654752f));
                    x1 = 0.5f * x1 * (1.f + erff(x1 * 0.70710678118654752f));
                    *reinterpret_cast<__half2*>(
                        reinterpret_cast<__half*>(J.C) + (size_t)m * (size_t)J.N + n) =
                        __floats2half2_rn(x0, x1);
                } else {
#pragma unroll
                    for (int j = 0; j < 2; j++) {
                        float x = v[h * 2 + j];
                        const int nn = n + j;
                        if (J.mode == 1) x *= J.scale;
                        else if (J.mode == 2) x = fmaxf(x, 0.f);
                        else if (J.mode == 4) x += J.R[((size_t)(m >> 12) * 256 + nn) * 4096 + (m & 4095)];
                        else if (J.mode == 5) x += J.R[(size_t)m * 256 + nn];
                        if (J.mode == 5)
                            J.C[((size_t)(m >> 12) * 256 + nn) * 4096 + (m & 4095)] = x;
                        else
                            J.C[(size_t)m * (size_t)J.N + nn] = x;
                    }
                }
            }
        }
    }
}

// ---------------- offset head ----------------
__global__ void off2_k(const float* __restrict__ h1, const float* __restrict__ w,
                       const float* __restrict__ bias, float* __restrict__ offs) {
    int id = blockIdx.x * blockDim.x + threadIdx.x;
    if (id >= MTOT * 18) return;
    int m = id / 18, n = id - m * 18;
    const float4* a = reinterpret_cast<const float4*>(h1 + (size_t)m * 256);
    const float4* ww = reinterpret_cast<const float4*>(w + (size_t)n * 256);
    float s = bias[n];
#pragma unroll 8
    for (int k = 0; k < 64; k++) {
        float4 av = a[k], wv = ww[k];
        s += av.x * wv.x + av.y * wv.y + av.z * wv.z + av.w * wv.w;
    }
    offs[id] = s;
}

// ---------------- fused bilinear-sample + 9-way attention (fp16 out) ----------------
#define LOAD8(dst, ptr)                                                     \
    {                                                                       \
        float4 _u0 = *reinterpret_cast<const float4*>(ptr);                 \
        float4 _u1 = *reinterpret_cast<const float4*>((ptr) + 4);           \
        dst[0] = _u0.x; dst[1] = _u0.y; dst[2] = _u0.z; dst[3] = _u0.w;     \
        dst[4] = _u1.x; dst[5] = _u1.y; dst[6] = _u1.z; dst[7] = _u1.w;     \
    }

__global__ void __launch_bounds__(256) attn_k(
    const float* __restrict__ qb, const float* __restrict__ kv,
    const float* __restrict__ offs, __half* __restrict__ outp) {
    __shared__ float sh[8][9][8];
    const int warp = threadIdx.x >> 5, lane = threadIdx.x & 31;
    const int p = blockIdx.x * 8 + warp;
    const int b = p >> 12, s = p & 4095, y = s >> 6, x = s & 63;
    const float* kvb = kv + (((size_t)b << 12) << 9);

    float qr[8];
    LOAD8(qr, qb + (size_t)p * 256 + lane * 8);

    for (int o = 0; o < 9; o++) {
        int ys = y + o / 3 - 1, xs = x + o % 3 - 1;
        float prod[8] = {0.f, 0.f, 0.f, 0.f, 0.f, 0.f, 0.f, 0.f};
        if (ys >= 0 && ys < 64 && xs >= 0 && xs < 64) {
            const float* op = offs + (size_t)((b << 12) + (ys << 6) + xs) * 18 + 2 * o;
            float px = op[0], py = op[1];
            float y0f = floorf(py), x0f = floorf(px);
            float wy = py - y0f, wx = px - x0f;
            int y0 = (int)y0f, x0 = (int)x0f;
            float w00 = (1.f - wy) * (1.f - wx), w01 = (1.f - wy) * wx;
            float w10 = wy * (1.f - wx), w11 = wy * wx;
            bool vy0 = (y0 >= 0) && (y0 < 64), vy1 = (y0 + 1 >= 0) && (y0 + 1 < 64);
            bool vx0 = (x0 >= 0) && (x0 < 64), vx1 = (x0 + 1 >= 0) && (x0 + 1 < 64);
            w00 = (vy0 && vx0) ? w00 : 0.f; w01 = (vy0 && vx1) ? w01 : 0.f;
            w10 = (vy1 && vx0) ? w10 : 0.f; w11 = (vy1 && vx1) ? w11 : 0.f;
            int y0c = min(max(y0, 0), 63), y1c = min(max(y0 + 1, 0), 63);
            int x0c = min(max(x0, 0), 63), x1c = min(max(x0 + 1, 0), 63);
            float c00[8], c01[8], c10[8], c11[8];
            LOAD8(c00, kvb + ((size_t)((y0c << 6) + x0c) << 9) + lane * 8);
            LOAD8(c01, kvb + ((size_t)((y0c << 6) + x1c) << 9) + lane * 8);
            LOAD8(c10, kvb + ((size_t)((y1c << 6) + x0c) << 9) + lane * 8);
            LOAD8(c11, kvb + ((size_t)((y1c << 6) + x1c) << 9) + lane * 8);
#pragma unroll
            for (int h = 0; h < 8; h++) {
                float kvv = w00 * c00[h] + w01 * c01[h] + w10 * c10[h] + w11 * c11[h];
                prod[h] = qr[h] * kvv;
            }
        }
#pragma unroll
        for (int off = 16; off > 0; off >>= 1)
#pragma unroll
            for (int h = 0; h < 8; h++)
                prod[h] += __shfl_xor_sync(0xffffffffu, prod[h], off);
        if (lane == 0) {
#pragma unroll
            for (int h = 0; h < 8; h++) sh[warp][o][h] = prod[h];
        }
    }
    __syncwarp();
    if (lane < 8) {
        float e[9]; float mx = -1e30f;
#pragma unroll
        for (int o = 0; o < 9; o++) { e[o] = sh[warp][o][lane]; mx = fmaxf(mx, e[o]); }
        float sm = 0.f;
#pragma unroll
        for (int o = 0; o < 9; o++) { e[o] = expf(e[o] - mx); sm += e[o]; }
        float inv = 1.f / sm;
#pragma unroll
        for (int o = 0; o < 9; o++) sh[warp][o][lane] = e[o] * inv;
    }
    __syncwarp();
    float acc[8] = {0.f, 0.f, 0.f, 0.f, 0.f, 0.f, 0.f, 0.f};
    for (int o = 0; o < 9; o++) {
        int ys = y + o / 3 - 1, xs = x + o % 3 - 1;
        if (ys < 0 || ys >= 64 || xs < 0 || xs >= 64) continue;
        const float* op = offs + (size_t)((b << 12) + (ys << 6) + xs) * 18 + 2 * o;
        float px = op[0], py = op[1];
        float y0f = floorf(py), x0f = floorf(px);
        float wy = py - y0f, wx = px - x0f;
        int y0 = (int)y0f, x0 = (int)x0f;
        float w00 = (1.f - wy) * (1.f - wx), w01 = (1.f - wy) * wx;
        float w10 = wy * (1.f - wx), w11 = wy * wx;
        bool vy0 = (y0 >= 0) && (y0 < 64), vy1 = (y0 + 1 >= 0) && (y0 + 1 < 64);
        bool vx0 = (x0 >= 0) && (x0 < 64), vx1 = (x0 + 1 >= 0) && (x0 + 1 < 64);
        w00 = (vy0 && vx0) ? w00 : 0.f; w01 = (vy0 && vx1) ? w01 : 0.f;
        w10 = (vy1 && vx0) ? w10 : 0.f; w11 = (vy1 && vx1) ? w11 : 0.f;
        int y0c = min(max(y0, 0), 63), y1c = min(max(y0 + 1, 0), 63);
        int x0c = min(max(x0, 0), 63), x1c = min(max(x0 + 1, 0), 63);
        float c00[8], c01[8], c10[8], c11[8];
        LOAD8(c00, kvb + ((size_t)((y0c << 6) + x0c) << 9) + 256 + lane * 8);
        LOAD8(c01, kvb + ((size_t)((y0c << 6) + x1c) << 9) + 256 + lane * 8);
        LOAD8(c10, kvb + ((size_t)((y1c << 6) + x0c) << 9) + 256 + lane * 8);
        LOAD8(c11, kvb + ((size_t)((y1c << 6) + x1c) << 9) + 256 + lane * 8);
#pragma unroll
        for (int h = 0; h < 8; h++) {
            float vv = w00 * c00[h] + w01 * c01[h] + w10 * c10[h] + w11 * c11[h];
            acc[h] += sh[warp][o][h] * vv;
        }
    }
    __half2 h0 = __floats2half2_rn(acc[0], acc[1]);
    __half2 h1 = __floats2half2_rn(acc[2], acc[3]);
    __half2 h2 = __floats2half2_rn(acc[4], acc[5]);
    __half2 h3 = __floats2half2_rn(acc[6], acc[7]);
    uint4 pk;
    pk.x = *reinterpret_cast<uint32_t*>(&h0);
    pk.y = *reinterpret_cast<uint32_t*>(&h1);
    pk.z = *reinterpret_cast<uint32_t*>(&h2);
    pk.w = *reinterpret_cast<uint32_t*>(&h3);
    *reinterpret_cast<uint4*>(outp + (size_t)p * 256 + lane * 8) = pk;
}

// ---------------- host ----------------
extern "C" void kernel_launch(void* const* d_in, const int* in_sizes, int n_in,
                              void* d_out, int out_size) {
    const float* x_q    = (const float*)d_in[0];
    const float* x_kv   = (const float*)d_in[1];
    const float* n1w    = (const float*)d_in[2];
    const float* n1b    = (const float*)d_in[3];
    const float* q_w    = (const float*)d_in[4];
    const float* q_b    = (const float*)d_in[5];
    const float* kv_w   = (const float*)d_in[6];
    const float* kv_b   = (const float*)d_in[7];
    const float* off1_w = (const float*)d_in[8];
    const float* off1_b = (const float*)d_in[9];
    const float* off2_w = (const float*)d_in[10];
    const float* off2_b = (const float*)d_in[11];
    const float* proj_w = (const float*)d_in[12];
    const float* proj_b = (const float*)d_in[13];
    const float* n2w    = (const float*)d_in[14];
    const float* n2b    = (const float*)d_in[15];
    const float* fc1_w  = (const float*)d_in[16];
    const float* fc1_b  = (const float*)d_in[17];
    const float* fc2_w  = (const float*)d_in[18];
    const float* fc2_b  = (const float*)d_in[19];
    float* out = (float*)d_out;

    __half *xall, *att, *xn2, *hid, *wr, *wh;
    float *qb, *kvb, *h1, *offs, *xres, *st1, *st2;
    float2* part;
    cudaGetSymbolAddress((void**)&xall, g_xall);
    cudaGetSymbolAddress((void**)&qb,   g_q);
    cudaGetSymbolAddress((void**)&kvb,  g_kv);
    cudaGetSymbolAddress((void**)&h1,   g_h1);
    cudaGetSymbolAddress((void**)&offs, g_offs);
    cudaGetSymbolAddress((void**)&att,  g_att);
    cudaGetSymbolAddress((void**)&xres, g_xres);
    cudaGetSymbolAddress((void**)&xn2,  g_xn2);
    cudaGetSymbolAddress((void**)&hid,  g_hid);
    cudaGetSymbolAddress((void**)&wr,   g_wr);
    cudaGetSymbolAddress((void**)&wh,   g_wh);
    cudaGetSymbolAddress((void**)&part, g_part);
    cudaGetSymbolAddress((void**)&st1,  g_st1);
    cudaGetSymbolAddress((void**)&st2,  g_st2);

    __half* qwh  = wh;                      // 65536
    __half* kvwh = qwh  + 65536;            // 131072
    __half* pwh  = kvwh + 131072;           // 65536
    __half* f1wh = pwh  + 65536;            // 262144
    __half* f2wh = f1wh + 262144;           // 262144

    cudaFuncSetAttribute(gemm_tc, cudaFuncAttributeMaxDynamicSharedMemorySize, SMEM_REQ);

    repack_k<<<4608, 256>>>(off1_w, wr);
    f2h_k<<<256, 256>>>(q_w,    qwh,  65536);
    f2h_k<<<512, 256>>>(kv_w,   kvwh, 131072);
    f2h_k<<<256, 256>>>(proj_w, pwh,  65536);
    f2h_k<<<1024, 256>>>(fc1_w, f1wh, 262144);
    f2h_k<<<1024, 256>>>(fc2_w, f2wh, 262144);

    gn_p1<<<256, 256>>>(x_q, x_kv, part);
    gn_p2<<<1, 256>>>(part, st1, 8);
    norm_pack_k<<<dim3(128, 8, 8), dim3(32, 8)>>>(x_q, x_kv, st1, n1w, n1b, xall);

    GJob zero = {};
    // fused q + kv + conv (conv first)
    {
        GJob jc  = {xall,       wr,   off1_b, h1,  nullptr, 256, 4608, 512, 2, 1, 0.f};
        GJob jkv = {xall + 256, kvwh, kv_b,   kvb, nullptr, 512, 256,  512, 0, 0, 0.f};
        GJob jq  = {xall,       qwh,  q_b,    qb,  nullptr, 256, 256,  512, 1, 0,
                    0.17677669529663689f};
        gemm_tc<<<1024, 256, SMEM_REQ>>>(jc, jkv, jq, 256, 768);
    }
    off2_k<<<(MTOT * 18) / 256, 256>>>(h1, off2_w, off2_b, offs);
    attn_k<<<2048, 256>>>(qb, kvb, offs, att);
    // xres = x_q + att @ proj_w^T + b
    {
        GJob jp = {att, pwh, proj_b, xres, x_q, 256, 256, 256, 4, 0, 0.f};
        gemm_tc<<<256, 256, SMEM_REQ>>>(jp, zero, zero, 256, 256);
    }
    gn_p1<<<128, 256>>>(xres, xres, part);
    gn_p2<<<1, 256>>>(part, st2, 4);
    norm2_k<<<(MTOT * 256) / 256, 256>>>(xres, st2, n2w, n2b, xn2);
    // hid = gelu(xn2 @ fc1_w^T + b) -> half
    {
        GJob jf1 = {xn2, f1wh, fc1_b, (float*)hid, nullptr, 1024, 256, 256, 3, 0, 0.f};
        gemm_tc<<<1024, 256, SMEM_REQ>>>(jf1, zero, zero, 1024, 1024);
    }
    // out(NCHW) = xres + hid @ fc2_w^T + b
    {
        GJob jf2 = {hid, f2wh, fc2_b, out, xres, 256, 1024, 1024, 5, 0, 0.f};
        gemm_tc<<<256, 256, SMEM_REQ>>>(jf2, zero, zero, 256, 256);
    }
}